// round 1
// baseline (speedup 1.0000x reference)
#include <cuda_runtime.h>
#include <math.h>

// Problem constants
#define B_    2
#define N_    1024
#define D_    512
#define H_    8
#define DH_   64
#define HD_   512
#define FF_   2048
#define DEPTH_ 4
#define BN_TOK (B_*N_)          // 2048 token rows
#define SCALE_ 0.125f           // DH^-0.5

// ---------------------------------------------------------------------------
// Scratch (static __device__ arrays; no allocation allowed)
// ---------------------------------------------------------------------------
__device__ float g_xbuf [BN_TOK * D_];        // running residual x
__device__ float g_xn   [BN_TOK * D_];        // layernorm output (shared ln1/ln2)
__device__ float g_qkv  [BN_TOK * 3 * HD_];   // qkv projection
__device__ float g_wsum [BN_TOK * HD_];       // r_t@w_kt + r_c@w_kc + r_p@w_kp
__device__ float g_AC   [B_*H_*N_*N_];        // content scores  (b,h,i,j)
__device__ float g_S    [B_*H_*N_*N_];        // pre-shift pos scores (b,h,i,j)
__device__ float g_obh  [BN_TOK * HD_];       // attention output (b,i, h*DH+d)
__device__ float g_h1   [BN_TOK * FF_];       // FF hidden

// ---------------------------------------------------------------------------
// LayerNorm: one block (256 threads) per row of D_=512
// ---------------------------------------------------------------------------
__global__ void ln_kernel(const float* __restrict__ x,
                          const float* __restrict__ g,
                          const float* __restrict__ b,
                          float* __restrict__ out) {
    int row = blockIdx.x;
    int t = threadIdx.x;
    const float* xr = x + (size_t)row * D_;
    __shared__ float red[256];

    float v0 = xr[t];
    float v1 = xr[t + 256];
    red[t] = v0 + v1;
    __syncthreads();
    for (int o = 128; o > 0; o >>= 1) {
        if (t < o) red[t] += red[t + o];
        __syncthreads();
    }
    float mean = red[0] * (1.0f / D_);
    __syncthreads();

    float d0 = v0 - mean, d1 = v1 - mean;
    red[t] = d0 * d0 + d1 * d1;
    __syncthreads();
    for (int o = 128; o > 0; o >>= 1) {
        if (t < o) red[t] += red[t + o];
        __syncthreads();
    }
    float inv = rsqrtf(red[0] * (1.0f / D_) + 1e-5f);

    out[(size_t)row * D_ + t]       = d0 * inv * g[t]       + b[t];
    out[(size_t)row * D_ + t + 256] = d1 * inv * g[t + 256] + b[t + 256];
}

// ---------------------------------------------------------------------------
// Generic SGEMM: C[M,N] = A[M,K] @ B[K,N]  (+accum / +bias / +residual / gelu)
// Block tile 128x64, K-chunk 16, 256 threads, 8x4 per-thread microtile.
// flags: bit0 = accumulate into C, bit1 = exact gelu epilogue
// ---------------------------------------------------------------------------
__global__ void sgemm_kernel(const float* __restrict__ A,
                             const float* __restrict__ Bm,
                             float* __restrict__ C,
                             int M, int N, int K,
                             const float* __restrict__ bias,
                             const float* __restrict__ res,
                             int flags) {
    __shared__ float As[16][128 + 4];
    __shared__ float Bs[16][64 + 4];
    int tid = threadIdx.y * 16 + threadIdx.x;
    int row0 = blockIdx.y * 128;
    int col0 = blockIdx.x * 64;

    float acc[8][4];
#pragma unroll
    for (int i = 0; i < 8; i++)
#pragma unroll
        for (int j = 0; j < 4; j++) acc[i][j] = 0.f;

    for (int k0 = 0; k0 < K; k0 += 16) {
#pragma unroll
        for (int t = 0; t < 8; t++) {
            int idx = tid + t * 256;
            int m = idx >> 4, k = idx & 15;
            int gr = row0 + m;
            As[k][m] = (gr < M) ? A[(size_t)gr * K + k0 + k] : 0.f;
        }
#pragma unroll
        for (int t = 0; t < 4; t++) {
            int idx = tid + t * 256;
            int kk = idx >> 6, n = idx & 63;
            int gc = col0 + n;
            Bs[kk][n] = (gc < N) ? Bm[(size_t)(k0 + kk) * N + gc] : 0.f;
        }
        __syncthreads();
#pragma unroll
        for (int kk = 0; kk < 16; kk++) {
            float a[8], bb[4];
#pragma unroll
            for (int i = 0; i < 8; i++) a[i] = As[kk][threadIdx.y * 8 + i];
#pragma unroll
            for (int j = 0; j < 4; j++) bb[j] = Bs[kk][threadIdx.x * 4 + j];
#pragma unroll
            for (int i = 0; i < 8; i++)
#pragma unroll
                for (int j = 0; j < 4; j++) acc[i][j] += a[i] * bb[j];
        }
        __syncthreads();
    }

#pragma unroll
    for (int i = 0; i < 8; i++) {
        int r = row0 + threadIdx.y * 8 + i;
        if (r >= M) continue;
#pragma unroll
        for (int j = 0; j < 4; j++) {
            int c = col0 + threadIdx.x * 4 + j;
            if (c >= N) continue;
            float v = acc[i][j];
            size_t o = (size_t)r * N + c;
            if (flags & 1) v += C[o];
            if (bias) v += bias[c];
            if (res) v += res[o];
            if (flags & 2) v = 0.5f * v * (1.0f + erff(v * 0.70710678118654752f));
            C[o] = v;
        }
    }
}

// ---------------------------------------------------------------------------
// Attention scores: AC[b,h,i,j] = (q+bias_pf)·k   and   S[b,h,i,j] = (q+bias_pf)·wsum
// q,k from g_qkv (strided), wsum from g_wsum. Tile 64x64 over (i,j), K=DH=64.
// ---------------------------------------------------------------------------
__global__ void scores_kernel(const float* __restrict__ qkv,
                              const float* __restrict__ bias_pf,
                              const float* __restrict__ wsum,
                              float* __restrict__ AC,
                              float* __restrict__ S) {
    int bh = blockIdx.z;
    int b = bh >> 3, h = bh & 7;
    int i0 = blockIdx.y * 64, j0 = blockIdx.x * 64;
    __shared__ float qs[16][68], ks[16][68], ws[16][68];
    int tid = threadIdx.y * 16 + threadIdx.x;

    float accA[4][4], accS[4][4];
#pragma unroll
    for (int i = 0; i < 4; i++)
#pragma unroll
        for (int j = 0; j < 4; j++) { accA[i][j] = 0.f; accS[i][j] = 0.f; }

    const float* qb = qkv + (size_t)b * N_ * 3 * HD_ + h * DH_;
    const float* kb = qkv + (size_t)b * N_ * 3 * HD_ + HD_ + h * DH_;
    const float* wb = wsum + (size_t)b * N_ * HD_ + h * DH_;

    for (int d0 = 0; d0 < DH_; d0 += 16) {
#pragma unroll
        for (int t = 0; t < 4; t++) {
            int idx = tid + t * 256;
            int r = idx >> 4, c = idx & 15;
            qs[c][r] = qb[(size_t)(i0 + r) * 3 * HD_ + d0 + c] + bias_pf[h * DH_ + d0 + c];
            ks[c][r] = kb[(size_t)(j0 + r) * 3 * HD_ + d0 + c];
            ws[c][r] = wb[(size_t)(j0 + r) * HD_ + d0 + c];
        }
        __syncthreads();
#pragma unroll
        for (int kk = 0; kk < 16; kk++) {
            float a[4], bk[4], bw[4];
#pragma unroll
            for (int i = 0; i < 4; i++) a[i] = qs[kk][threadIdx.y * 4 + i];
#pragma unroll
            for (int j = 0; j < 4; j++) { bk[j] = ks[kk][threadIdx.x * 4 + j];
                                          bw[j] = ws[kk][threadIdx.x * 4 + j]; }
#pragma unroll
            for (int i = 0; i < 4; i++)
#pragma unroll
                for (int j = 0; j < 4; j++) {
                    accA[i][j] += a[i] * bk[j];
                    accS[i][j] += a[i] * bw[j];
                }
        }
        __syncthreads();
    }

    size_t base = (size_t)bh * N_;
#pragma unroll
    for (int i = 0; i < 4; i++) {
        int ii = i0 + threadIdx.y * 4 + i;
#pragma unroll
        for (int j = 0; j < 4; j++) {
            int jj = j0 + threadIdx.x * 4 + j;
            size_t o = (base + ii) * N_ + jj;
            AC[o] = accA[i][j];
            S[o]  = accS[i][j];
        }
    }
}

// ---------------------------------------------------------------------------
// Fused rel_shift gather + softmax over heads (axis=-1 is h!).
// attn[b,h,i,j] written directly in the output layout (b,h,q,k).
// shift map (derived from pad/reshape/slice):
//   j <= i   : S[i, N-1-i+j]
//   j == i+1 : 0
//   j >  i+1 : S[i+1, j-i-2]
// ---------------------------------------------------------------------------
__global__ void softmax_shift_kernel(const float* __restrict__ AC,
                                     const float* __restrict__ S,
                                     float* __restrict__ attn) {
    int t = blockIdx.x * blockDim.x + threadIdx.x;
    if (t >= B_ * N_ * N_) return;
    int j = t & (N_ - 1);
    int i = (t >> 10) & (N_ - 1);
    int b = t >> 20;

    float vals[H_];
    float mx = -1e30f;
#pragma unroll
    for (int h = 0; h < H_; h++) {
        size_t base = (size_t)(b * H_ + h) * N_;
        float ac = AC[(base + i) * N_ + j];
        float s;
        if (j <= i)           s = S[(base + i) * N_ + (N_ - 1 - i + j)];
        else if (j == i + 1)  s = 0.f;
        else                  s = S[(base + i + 1) * N_ + (j - i - 2)];
        float v = (ac + s * (1.0f / 3.0f)) * SCALE_;
        vals[h] = v;
        mx = fmaxf(mx, v);
    }
    float sum = 0.f;
#pragma unroll
    for (int h = 0; h < H_; h++) { vals[h] = expf(vals[h] - mx); sum += vals[h]; }
    float inv = 1.0f / sum;
#pragma unroll
    for (int h = 0; h < H_; h++)
        attn[((size_t)(b * H_ + h) * N_ + i) * N_ + j] = vals[h] * inv;
}

// ---------------------------------------------------------------------------
// attn @ V : out[b,i,h*DH+d] = sum_j attn[b,h,i,j] * v[b,h,j,d]
// One block per (bh, 64-row i tile); 64x64 output tile, K=N_ in chunks of 16.
// ---------------------------------------------------------------------------
__global__ void av_kernel(const float* __restrict__ attn,
                          const float* __restrict__ qkv,
                          float* __restrict__ obh) {
    int bh = blockIdx.y;
    int b = bh >> 3, h = bh & 7;
    int i0 = blockIdx.x * 64;
    __shared__ float As[16][68];   // [j-chunk][i]
    __shared__ float Vs[16][68];   // [j-chunk][d]
    int tid = threadIdx.y * 16 + threadIdx.x;

    float acc[4][4];
#pragma unroll
    for (int i = 0; i < 4; i++)
#pragma unroll
        for (int j = 0; j < 4; j++) acc[i][j] = 0.f;

    const float* ab = attn + (size_t)bh * N_ * N_;
    const float* vb = qkv + (size_t)b * N_ * 3 * HD_ + 2 * HD_ + h * DH_;

    for (int j0 = 0; j0 < N_; j0 += 16) {
#pragma unroll
        for (int t = 0; t < 4; t++) {
            int idx = tid + t * 256;
            int r = idx >> 4, c = idx & 15;
            As[c][r] = ab[(size_t)(i0 + r) * N_ + j0 + c];
        }
#pragma unroll
        for (int t = 0; t < 4; t++) {
            int idx = tid + t * 256;
            int r = idx >> 6, c = idx & 63;
            Vs[r][c] = vb[(size_t)(j0 + r) * 3 * HD_ + c];
        }
        __syncthreads();
#pragma unroll
        for (int kk = 0; kk < 16; kk++) {
            float a[4], v[4];
#pragma unroll
            for (int i = 0; i < 4; i++) a[i] = As[kk][threadIdx.y * 4 + i];
#pragma unroll
            for (int j = 0; j < 4; j++) v[j] = Vs[kk][threadIdx.x * 4 + j];
#pragma unroll
            for (int i = 0; i < 4; i++)
#pragma unroll
                for (int j = 0; j < 4; j++) acc[i][j] += a[i] * v[j];
        }
        __syncthreads();
    }

#pragma unroll
    for (int i = 0; i < 4; i++) {
        int ii = i0 + threadIdx.y * 4 + i;
#pragma unroll
        for (int j = 0; j < 4; j++) {
            int dd = threadIdx.x * 4 + j;
            obh[(size_t)(b * N_ + ii) * HD_ + h * DH_ + dd] = acc[i][j];
        }
    }
}

// ---------------------------------------------------------------------------
// Host-side orchestration
// ---------------------------------------------------------------------------
extern "C" void kernel_launch(void* const* d_in, const int* in_sizes, int n_in,
                              void* d_out, int out_size) {
    (void)in_sizes; (void)n_in; (void)out_size;
    const float* x       = (const float*)d_in[0];
    const float* r_t     = (const float*)d_in[1];
    const float* r_c     = (const float*)d_in[2];
    const float* r_p     = (const float*)d_in[3];
    const float* bias_pf = (const float*)d_in[4];
    const float* ln1_g   = (const float*)d_in[5];
    const float* ln1_b   = (const float*)d_in[6];
    const float* w_qkv   = (const float*)d_in[7];
    const float* w_out   = (const float*)d_in[8];
    const float* b_out   = (const float*)d_in[9];
    const float* w_kt    = (const float*)d_in[10];
    const float* w_kc    = (const float*)d_in[11];
    const float* w_kp    = (const float*)d_in[12];
    const float* ln2_g   = (const float*)d_in[13];
    const float* ln2_b   = (const float*)d_in[14];
    const float* w_ff1   = (const float*)d_in[15];
    const float* b_ff1   = (const float*)d_in[16];
    const float* w_ff2   = (const float*)d_in[17];
    const float* b_ff2   = (const float*)d_in[18];

    float* out      = (float*)d_out;
    float* attn_out = out + (size_t)BN_TOK * D_;  // attn lives in output (b,h,q,k)

    float *xbuf, *xn, *qkv, *wsum, *AC, *S, *obh, *h1;
    cudaGetSymbolAddress((void**)&xbuf, g_xbuf);
    cudaGetSymbolAddress((void**)&xn,   g_xn);
    cudaGetSymbolAddress((void**)&qkv,  g_qkv);
    cudaGetSymbolAddress((void**)&wsum, g_wsum);
    cudaGetSymbolAddress((void**)&AC,   g_AC);
    cudaGetSymbolAddress((void**)&S,    g_S);
    cudaGetSymbolAddress((void**)&obh,  g_obh);
    cudaGetSymbolAddress((void**)&h1,   g_h1);

    cudaMemcpyAsync(xbuf, x, sizeof(float) * BN_TOK * D_, cudaMemcpyDeviceToDevice);

    dim3 blk(16, 16);
    for (int l = 0; l < DEPTH_; l++) {
        // ln1
        ln_kernel<<<BN_TOK, 256>>>(xbuf, ln1_g + l * D_, ln1_b + l * D_, xn);
        // qkv = xn @ w_qkv[l]
        sgemm_kernel<<<dim3((3 * HD_) / 64, BN_TOK / 128), blk>>>(
            xn, w_qkv + (size_t)l * D_ * 3 * HD_, qkv,
            BN_TOK, 3 * HD_, D_, nullptr, nullptr, 0);
        // wsum = r_t@w_kt + r_c@w_kc + r_p@w_kp
        sgemm_kernel<<<dim3(HD_ / 64, BN_TOK / 128), blk>>>(
            r_t, w_kt + (size_t)l * D_ * HD_, wsum, BN_TOK, HD_, D_, nullptr, nullptr, 0);
        sgemm_kernel<<<dim3(HD_ / 64, BN_TOK / 128), blk>>>(
            r_c, w_kc + (size_t)l * D_ * HD_, wsum, BN_TOK, HD_, D_, nullptr, nullptr, 1);
        sgemm_kernel<<<dim3(HD_ / 64, BN_TOK / 128), blk>>>(
            r_p, w_kp + (size_t)l * D_ * HD_, wsum, BN_TOK, HD_, D_, nullptr, nullptr, 1);
        // AC and S (pre-shift position scores)
        scores_kernel<<<dim3(N_ / 64, N_ / 64, B_ * H_), blk>>>(qkv, bias_pf, wsum, AC, S);
        // rel_shift + softmax over heads -> attn (output layout b,h,q,k)
        softmax_shift_kernel<<<(B_ * N_ * N_ + 255) / 256, 256>>>(AC, S, attn_out);
        // attn @ v -> obh (b, i, h*DH+d)
        av_kernel<<<dim3(N_ / 64, B_ * H_), blk>>>(attn_out, qkv, obh);
        // x = obh @ w_out + b_out + x
        sgemm_kernel<<<dim3(D_ / 64, BN_TOK / 128), blk>>>(
            obh, w_out + (size_t)l * HD_ * D_, xbuf,
            BN_TOK, D_, HD_, b_out + l * D_, xbuf, 0);
        // ln2
        ln_kernel<<<BN_TOK, 256>>>(xbuf, ln2_g + l * D_, ln2_b + l * D_, xn);
        // h1 = gelu(xn @ w_ff1 + b_ff1)
        sgemm_kernel<<<dim3(FF_ / 64, BN_TOK / 128), blk>>>(
            xn, w_ff1 + (size_t)l * D_ * FF_, h1,
            BN_TOK, FF_, D_, b_ff1 + l * FF_, nullptr, 2);
        // x = h1 @ w_ff2 + b_ff2 + x
        sgemm_kernel<<<dim3(D_ / 64, BN_TOK / 128), blk>>>(
            h1, w_ff2 + (size_t)l * FF_ * D_, xbuf,
            BN_TOK, D_, FF_, b_ff2 + l * D_, xbuf, 0);
    }

    cudaMemcpyAsync(out, xbuf, sizeof(float) * BN_TOK * D_, cudaMemcpyDeviceToDevice);
}

// round 8
// speedup vs baseline: 1.5562x; 1.5562x over previous
#include <cuda_runtime.h>
#include <math.h>
#include <stdint.h>

// Problem constants
#define B_    2
#define N_    1024
#define D_    512
#define H_    8
#define DH_   64
#define HD_   512
#define FF_   2048
#define DEPTH_ 4
#define BN_TOK (B_*N_)
#define SCALE_ 0.125f

// ---------------------------------------------------------------------------
// Scratch (static __device__ arrays; no allocation allowed)
// ---------------------------------------------------------------------------
__device__ float g_xbuf [BN_TOK * D_];
__device__ float g_xn   [BN_TOK * D_];
__device__ float g_qkv  [BN_TOK * 3 * HD_];
__device__ float g_wsum [BN_TOK * HD_];
__device__ float g_AC   [B_*H_*N_*N_];
__device__ float g_S    [B_*H_*N_*N_];
__device__ float g_obh  [BN_TOK * HD_];
__device__ float g_h1   [BN_TOK * FF_];

// ---------------------------------------------------------------------------
// tf32 helpers
// ---------------------------------------------------------------------------
__device__ __forceinline__ uint32_t f2tf32(float x) {
    uint32_t u;
    asm("cvt.rna.tf32.f32 %0, %1;" : "=r"(u) : "f"(x));
    return u;
}

__device__ __forceinline__ void mma_tf32(float& d0, float& d1, float& d2, float& d3,
                                         uint32_t a0, uint32_t a1, uint32_t a2, uint32_t a3,
                                         uint32_t b0, uint32_t b1) {
    asm volatile(
        "mma.sync.aligned.m16n8k8.row.col.f32.tf32.tf32.f32 "
        "{%0,%1,%2,%3}, {%4,%5,%6,%7}, {%8,%9}, {%0,%1,%2,%3};"
        : "+f"(d0), "+f"(d1), "+f"(d2), "+f"(d3)
        : "r"(a0), "r"(a1), "r"(a2), "r"(a3), "r"(b0), "r"(b1));
}

// ---------------------------------------------------------------------------
// Generic warp-MMA tf32 GEMM.
//   C[z][m][n] = sum_p A_p[z][m][k] * B_p[z][n][k]   (B K-major if btrans=0;
//                B source (K,N) row-major, transposed on load, if btrans=1)
// Block: 256 threads, tile 128 x NT (NT = 128 or 64), K-chunk 32.
// Warp tiles: NT=128 -> 8 warps of 32x64 (4x2); NT=64 -> 8 warps of 16x64.
// z batching: offsets (z>>3)*Xbb + (z&7)*Xbh per tensor.
// abias: optional per-K bias on A (bias_pf), indexed abias[(z&7)*64 + k].
// flags: 1=col bias, 2=residual add, 4=exact gelu.
// ---------------------------------------------------------------------------
template<int NT>
__global__ void __launch_bounds__(256, 2) mma_gemm(
    const float* a0p, const float* a1p, const float* a2p,
    const float* b0p, const float* b1p, const float* b2p,
    int npairs, int K, int lda, int ldb, int btrans,
    long long abb, long long abh, long long bbb, long long bbh,
    const float* abias,
    float* C, int ldc, long long cbb, long long cbh,
    const float* bias, const float* resid, int flags)
{
    __shared__ uint32_t As[128][36];
    __shared__ uint32_t Bs[NT][36];

    constexpr int MT = (NT == 128) ? 2 : 1;   // 16-row m-tiles per warp
    int tid = threadIdx.x;
    int warp = tid >> 5, lane = tid & 31;
    int gr = lane >> 2, gc = lane & 3;

    int wm  = (NT == 128) ? (warp & 3) * 32 : warp * 16;
    int wn0 = (NT == 128) ? (warp >> 2) * 64 : 0;

    int zb = blockIdx.z >> 3, zh = blockIdx.z & 7;
    long long aoff = (long long)zb * abb + (long long)zh * abh;
    long long boff = (long long)zb * bbb + (long long)zh * bbh;
    long long coff = (long long)zb * cbb + (long long)zh * cbh;
    int m0 = blockIdx.y * 128;
    int n0 = blockIdx.x * NT;

    float acc[MT][8][4];
#pragma unroll
    for (int mt = 0; mt < MT; mt++)
#pragma unroll
        for (int nt = 0; nt < 8; nt++)
#pragma unroll
            for (int q = 0; q < 4; q++) acc[mt][nt][q] = 0.f;

    int kchunks = K >> 5;
    int nch = npairs * kchunks;

    for (int c = 0; c < nch; c++) {
        int p = c / kchunks;
        int k0 = (c - p * kchunks) << 5;
        const float* Ab = (p == 0 ? a0p : (p == 1 ? a1p : a2p));
        const float* Bb = (p == 0 ? b0p : (p == 1 ? b1p : b2p));
        const float* Ap = Ab + aoff + (size_t)m0 * lda + k0;
        const float* ab = abias ? (abias + zh * DH_ + k0) : (const float*)0;

        // ---- A tile: 128 rows x 32 floats (row-major, K contiguous) ----
#pragma unroll
        for (int t = 0; t < 4; t++) {
            int i = tid + t * 256;
            int r = i >> 3, f = i & 7;                 // f = float4 index
            float4 v = *(const float4*)(Ap + (size_t)r * lda + f * 4);
            if (ab) {
                float4 bv = *(const float4*)(ab + f * 4);
                v.x += bv.x; v.y += bv.y; v.z += bv.z; v.w += bv.w;
            }
            uint32_t* dst = &As[r][f * 4];
            uint2 lo = { f2tf32(v.x), f2tf32(v.y) };
            uint2 hi = { f2tf32(v.z), f2tf32(v.w) };
            *(uint2*)dst = lo;
            *(uint2*)(dst + 2) = hi;
        }
        // ---- B tile: NT rows x 32 floats ----
        if (!btrans) {
            const float* Bsrc = Bb + boff + (size_t)n0 * ldb + k0;
#pragma unroll
            for (int t = 0; t < NT / 32; t++) {
                int i = tid + t * 256;
                int r = i >> 3, f = i & 7;
                float4 v = *(const float4*)(Bsrc + (size_t)r * ldb + f * 4);
                uint32_t* dst = &Bs[r][f * 4];
                uint2 lo = { f2tf32(v.x), f2tf32(v.y) };
                uint2 hi = { f2tf32(v.z), f2tf32(v.w) };
                *(uint2*)dst = lo;
                *(uint2*)(dst + 2) = hi;
            }
        } else {
            // source (K,N) row-major -> Bs[n][k]; coalesced over n
            const float* Bsrc = Bb + boff + (size_t)k0 * ldb + n0;
            int n = tid & (NT - 1);
            int kb = tid / NT;                         // 256/NT k-slots
            constexpr int KSTEP = 256 / NT;
#pragma unroll
            for (int t = 0; t < 32 / KSTEP; t++) {
                int k = kb + t * KSTEP;
                Bs[n][k] = f2tf32(Bsrc[(size_t)k * ldb + n]);
            }
        }
        __syncthreads();

        // ---- compute: 4 k-steps of m16n8k8 ----
#pragma unroll
        for (int ks = 0; ks < 4; ks++) {
            int k = ks * 8;
            uint32_t af[MT][4];
#pragma unroll
            for (int mt = 0; mt < MT; mt++) {
                int row = wm + mt * 16 + gr;
                af[mt][0] = As[row][k + gc];
                af[mt][1] = As[row + 8][k + gc];
                af[mt][2] = As[row][k + gc + 4];
                af[mt][3] = As[row + 8][k + gc + 4];
            }
#pragma unroll
            for (int nt = 0; nt < 8; nt++) {
                int col = wn0 + nt * 8 + gr;
                uint32_t b0 = Bs[col][k + gc];
                uint32_t b1 = Bs[col][k + gc + 4];
#pragma unroll
                for (int mt = 0; mt < MT; mt++)
                    mma_tf32(acc[mt][nt][0], acc[mt][nt][1], acc[mt][nt][2], acc[mt][nt][3],
                             af[mt][0], af[mt][1], af[mt][2], af[mt][3], b0, b1);
            }
        }
        __syncthreads();
    }

    // ---- epilogue ----
    float* Cp = C + coff;
    const float* Rp = resid ? (resid + coff) : (const float*)0;
#pragma unroll
    for (int mt = 0; mt < MT; mt++) {
#pragma unroll
        for (int half = 0; half < 2; half++) {
            int rr = m0 + wm + mt * 16 + gr + half * 8;
#pragma unroll
            for (int nt = 0; nt < 8; nt++) {
                int cc = n0 + wn0 + nt * 8 + 2 * gc;
                float v0 = acc[mt][nt][half * 2 + 0];
                float v1 = acc[mt][nt][half * 2 + 1];
                size_t o = (size_t)rr * ldc + cc;
                if (flags & 1) { v0 += bias[cc]; v1 += bias[cc + 1]; }
                if (flags & 2) { v0 += Rp[o]; v1 += Rp[o + 1]; }
                if (flags & 4) {
                    v0 = 0.5f * v0 * (1.0f + erff(v0 * 0.70710678118654752f));
                    v1 = 0.5f * v1 * (1.0f + erff(v1 * 0.70710678118654752f));
                }
                float2 w = { v0, v1 };
                *(float2*)(Cp + o) = w;
            }
        }
    }
}

// ---------------------------------------------------------------------------
// LayerNorm: one block (256 threads) per row of D_=512
// ---------------------------------------------------------------------------
__global__ void ln_kernel(const float* __restrict__ x,
                          const float* __restrict__ g,
                          const float* __restrict__ b,
                          float* __restrict__ out) {
    int row = blockIdx.x;
    int t = threadIdx.x;
    const float* xr = x + (size_t)row * D_;
    __shared__ float red[256];

    float v0 = xr[t];
    float v1 = xr[t + 256];
    red[t] = v0 + v1;
    __syncthreads();
    for (int o = 128; o > 0; o >>= 1) { if (t < o) red[t] += red[t + o]; __syncthreads(); }
    float mean = red[0] * (1.0f / D_);
    __syncthreads();

    float d0 = v0 - mean, d1 = v1 - mean;
    red[t] = d0 * d0 + d1 * d1;
    __syncthreads();
    for (int o = 128; o > 0; o >>= 1) { if (t < o) red[t] += red[t + o]; __syncthreads(); }
    float inv = rsqrtf(red[0] * (1.0f / D_) + 1e-5f);

    out[(size_t)row * D_ + t]       = d0 * inv * g[t]       + b[t];
    out[(size_t)row * D_ + t + 256] = d1 * inv * g[t + 256] + b[t + 256];
}

// ---------------------------------------------------------------------------
// Fused rel_shift gather + softmax over heads (axis=-1 is h!)
//   j <= i   : S[i, N-1-i+j];  j == i+1 : 0;  j > i+1 : S[i+1, j-i-2]
// ---------------------------------------------------------------------------
__global__ void softmax_shift_kernel(const float* __restrict__ AC,
                                     const float* __restrict__ S,
                                     float* __restrict__ attn) {
    int t = blockIdx.x * blockDim.x + threadIdx.x;
    if (t >= B_ * N_ * N_) return;
    int j = t & (N_ - 1);
    int i = (t >> 10) & (N_ - 1);
    int b = t >> 20;

    float vals[H_];
    float mx = -1e30f;
#pragma unroll
    for (int h = 0; h < H_; h++) {
        size_t base = (size_t)(b * H_ + h) * N_;
        float ac = AC[(base + i) * N_ + j];
        float s;
        if (j <= i)           s = S[(base + i) * N_ + (N_ - 1 - i + j)];
        else if (j == i + 1)  s = 0.f;
        else                  s = S[(base + i + 1) * N_ + (j - i - 2)];
        float v = (ac + s * (1.0f / 3.0f)) * SCALE_;
        vals[h] = v;
        mx = fmaxf(mx, v);
    }
    float sum = 0.f;
#pragma unroll
    for (int h = 0; h < H_; h++) { vals[h] = expf(vals[h] - mx); sum += vals[h]; }
    float inv = 1.0f / sum;
#pragma unroll
    for (int h = 0; h < H_; h++)
        attn[((size_t)(b * H_ + h) * N_ + i) * N_ + j] = vals[h] * inv;
}

// ---------------------------------------------------------------------------
// Host-side orchestration
// ---------------------------------------------------------------------------
extern "C" void kernel_launch(void* const* d_in, const int* in_sizes, int n_in,
                              void* d_out, int out_size) {
    (void)in_sizes; (void)n_in; (void)out_size;
    const float* x       = (const float*)d_in[0];
    const float* r_t     = (const float*)d_in[1];
    const float* r_c     = (const float*)d_in[2];
    const float* r_p     = (const float*)d_in[3];
    const float* bias_pf = (const float*)d_in[4];
    const float* ln1_g   = (const float*)d_in[5];
    const float* ln1_b   = (const float*)d_in[6];
    const float* w_qkv   = (const float*)d_in[7];
    const float* w_out   = (const float*)d_in[8];
    const float* b_out   = (const float*)d_in[9];
    const float* w_kt    = (const float*)d_in[10];
    const float* w_kc    = (const float*)d_in[11];
    const float* w_kp    = (const float*)d_in[12];
    const float* ln2_g   = (const float*)d_in[13];
    const float* ln2_b   = (const float*)d_in[14];
    const float* w_ff1   = (const float*)d_in[15];
    const float* b_ff1   = (const float*)d_in[16];
    const float* w_ff2   = (const float*)d_in[17];
    const float* b_ff2   = (const float*)d_in[18];

    float* out      = (float*)d_out;
    float* attn_out = out + (size_t)BN_TOK * D_;

    float *xbuf, *xn, *qkv, *wsum, *AC, *S, *obh, *h1;
    cudaGetSymbolAddress((void**)&xbuf, g_xbuf);
    cudaGetSymbolAddress((void**)&xn,   g_xn);
    cudaGetSymbolAddress((void**)&qkv,  g_qkv);
    cudaGetSymbolAddress((void**)&wsum, g_wsum);
    cudaGetSymbolAddress((void**)&AC,   g_AC);
    cudaGetSymbolAddress((void**)&S,    g_S);
    cudaGetSymbolAddress((void**)&obh,  g_obh);
    cudaGetSymbolAddress((void**)&h1,   g_h1);

    cudaMemcpyAsync(xbuf, x, sizeof(float) * BN_TOK * D_, cudaMemcpyDeviceToDevice);

    const long long NN = (long long)N_ * N_;
    const long long QKVB = (long long)N_ * 3 * HD_;

    for (int l = 0; l < DEPTH_; l++) {
        // ln1
        ln_kernel<<<BN_TOK, 256>>>(xbuf, ln1_g + l * D_, ln1_b + l * D_, xn);

        // qkv = xn @ w_qkv[l]           (M=2048, N=1536, K=512)
        mma_gemm<128><<<dim3(12, 16, 1), 256>>>(
            xn, 0, 0, w_qkv + (size_t)l * D_ * 3 * HD_, 0, 0,
            1, D_, D_, 3 * HD_, 1, 0, 0, 0, 0, 0,
            qkv, 3 * HD_, 0, 0, 0, 0, 0);

        // wsum = r_t@w_kt + r_c@w_kc + r_p@w_kp   (3-pair fused)
        mma_gemm<128><<<dim3(4, 16, 1), 256>>>(
            r_t, r_c, r_p,
            w_kt + (size_t)l * D_ * HD_, w_kc + (size_t)l * D_ * HD_, w_kp + (size_t)l * D_ * HD_,
            3, D_, D_, HD_, 1, 0, 0, 0, 0, 0,
            wsum, HD_, 0, 0, 0, 0, 0);

        // AC[b,h] = (q+bias_pf) @ k^T     (batched z=16, M=N=1024, K=64)
        mma_gemm<128><<<dim3(8, 8, 16), 256>>>(
            qkv, 0, 0, qkv + HD_, 0, 0,
            1, DH_, 3 * HD_, 3 * HD_, 0,
            QKVB, 64, QKVB, 64, bias_pf,
            AC, N_, 8 * NN, NN, 0, 0, 0);

        // S[b,h] = (q+bias_pf) @ wsum^T
        mma_gemm<128><<<dim3(8, 8, 16), 256>>>(
            qkv, 0, 0, wsum, 0, 0,
            1, DH_, 3 * HD_, HD_, 0,
            QKVB, 64, (long long)N_ * HD_, 64, bias_pf,
            S, N_, 8 * NN, NN, 0, 0, 0);

        // rel_shift + softmax over heads -> attn (output layout b,h,q,k)
        softmax_shift_kernel<<<(B_ * N_ * N_ + 255) / 256, 256>>>(AC, S, attn_out);

        // obh[b,i,h*64+d] = attn[b,h] @ v[b,h]   (batched z=16, M=1024, N=64, K=1024)
        mma_gemm<64><<<dim3(1, 8, 16), 256>>>(
            attn_out, 0, 0, qkv + 2 * HD_, 0, 0,
            1, N_, N_, 3 * HD_, 1,
            8 * NN, NN, QKVB, 64, 0,
            obh, HD_, (long long)N_ * HD_, 64, 0, 0, 0);

        // x = obh @ w_out + b_out + x
        mma_gemm<128><<<dim3(4, 16, 1), 256>>>(
            obh, 0, 0, w_out + (size_t)l * HD_ * D_, 0, 0,
            1, HD_, HD_, D_, 1, 0, 0, 0, 0, 0,
            xbuf, D_, 0, 0, b_out + l * D_, xbuf, 3);

        // ln2
        ln_kernel<<<BN_TOK, 256>>>(xbuf, ln2_g + l * D_, ln2_b + l * D_, xn);

        // h1 = gelu(xn @ w_ff1 + b_ff1)    (M=2048, N=2048, K=512)
        mma_gemm<128><<<dim3(16, 16, 1), 256>>>(
            xn, 0, 0, w_ff1 + (size_t)l * D_ * FF_, 0, 0,
            1, D_, D_, FF_, 1, 0, 0, 0, 0, 0,
            h1, FF_, 0, 0, b_ff1 + l * FF_, 0, 5);

        // x = h1 @ w_ff2 + b_ff2 + x       (M=2048, N=512, K=2048)
        mma_gemm<128><<<dim3(4, 16, 1), 256>>>(
            h1, 0, 0, w_ff2 + (size_t)l * FF_ * D_, 0, 0,
            1, FF_, FF_, D_, 1, 0, 0, 0, 0, 0,
            xbuf, D_, 0, 0, b_ff2 + l * D_, xbuf, 3);
    }

    cudaMemcpyAsync(out, xbuf, sizeof(float) * BN_TOK * D_, cudaMemcpyDeviceToDevice);
}

// round 10
// speedup vs baseline: 2.6516x; 1.7039x over previous
#include <cuda_runtime.h>
#include <math.h>
#include <stdint.h>

// Problem constants
#define B_    2
#define N_    1024
#define D_    512
#define H_    8
#define DH_   64
#define HD_   512
#define FF_   2048
#define DEPTH_ 4
#define BN_TOK (B_*N_)
#define SCALE_ 0.125f

// ---------------------------------------------------------------------------
// Scratch (static __device__ arrays; no allocation allowed)
// ---------------------------------------------------------------------------
__device__ float g_xbuf [BN_TOK * D_];
__device__ float g_xn   [BN_TOK * D_];
__device__ float g_qkv  [BN_TOK * 3 * HD_];
__device__ float g_wsum [BN_TOK * HD_];
__device__ float g_AC   [B_*H_*N_*N_];
__device__ float g_S    [B_*H_*N_*N_];
__device__ float g_obh  [BN_TOK * HD_];
__device__ float g_h1   [BN_TOK * FF_];

// ---------------------------------------------------------------------------
// helpers
// ---------------------------------------------------------------------------
__device__ __forceinline__ uint32_t f2tf32(float x) {
    uint32_t u;
    asm("cvt.rna.tf32.f32 %0, %1;" : "=r"(u) : "f"(x));
    return u;
}

__device__ __forceinline__ void mma_tf32(float& d0, float& d1, float& d2, float& d3,
                                         uint32_t a0, uint32_t a1, uint32_t a2, uint32_t a3,
                                         uint32_t b0, uint32_t b1) {
    asm volatile(
        "mma.sync.aligned.m16n8k8.row.col.f32.tf32.tf32.f32 "
        "{%0,%1,%2,%3}, {%4,%5,%6,%7}, {%8,%9}, {%0,%1,%2,%3};"
        : "+f"(d0), "+f"(d1), "+f"(d2), "+f"(d3)
        : "r"(a0), "r"(a1), "r"(a2), "r"(a3), "r"(b0), "r"(b1));
}

__device__ __forceinline__ void cpa16(uint32_t dst, const float* src) {
    asm volatile("cp.async.cg.shared.global [%0], [%1], 16;" :: "r"(dst), "l"(src));
}
#define CP_COMMIT() asm volatile("cp.async.commit_group;" ::: "memory")
#define CP_WAIT1()  asm volatile("cp.async.wait_group 1;" ::: "memory")
#define CP_WAIT0()  asm volatile("cp.async.wait_group 0;" ::: "memory")

// ---------------------------------------------------------------------------
// Generic warp-MMA tf32 GEMM with cp.async double-buffered pipeline.
//   C[z][m][n] = sum_p A_p[z][m][k] * B_p[z][n][k]
//   BT=0: B source K-major (N,K).  BT=1: B source (K,N) row-major.
// Block: 256 threads, tile 128 x NT, K-chunk 32.
// Smem layouts (f32, converted to tf32 at fragment load):
//   A: [128][36]  (bank = 4*gr + gc, bijective)
//   B BT=0: [NT][36]
//   B BT=1: [32][BSTRIDE], BSTRIDE=136 (NT=128) / 72 (NT=64)  (stride%32==8)
// flags: 1=col bias, 2=residual add, 4=exact gelu.
// ---------------------------------------------------------------------------
template<int NT, int BT>
__global__ void __launch_bounds__(256, 2) mma_gemm(
    const float* a0p, const float* a1p, const float* a2p,
    const float* b0p, const float* b1p, const float* b2p,
    int npairs, int K, int lda, int ldb,
    long long abb, long long abh, long long bbb, long long bbh,
    const float* abias,
    float* C, int ldc, long long cbb, long long cbh,
    const float* bias, const float* resid, int flags)
{
    extern __shared__ float smem[];
    constexpr int ASTRIDE = 36;
    constexpr int ASTG = 128 * ASTRIDE;                       // words / buffer
    constexpr int BSTRIDE = (BT == 0) ? 36 : ((NT == 128) ? 136 : 72);
    constexpr int BSTG = (BT == 0) ? NT * 36 : 32 * BSTRIDE;  // words / buffer

    float* Asf = smem;                    // 2 * ASTG
    float* Bsf = smem + 2 * ASTG;         // 2 * BSTG
    uint32_t smem_u32 = (uint32_t)__cvta_generic_to_shared(smem);
    uint32_t a_u32 = smem_u32;
    uint32_t b_u32 = smem_u32 + 2 * ASTG * 4;

    constexpr int MT = (NT == 128) ? 2 : 1;
    int tid = threadIdx.x;
    int warp = tid >> 5, lane = tid & 31;
    int gr = lane >> 2, gc = lane & 3;

    int wm  = (NT == 128) ? (warp & 3) * 32 : warp * 16;
    int wn0 = (NT == 128) ? (warp >> 2) * 64 : 0;

    int zb = blockIdx.z >> 3, zh = blockIdx.z & 7;
    long long aoff = (long long)zb * abb + (long long)zh * abh;
    long long boff = (long long)zb * bbb + (long long)zh * bbh;
    long long coff = (long long)zb * cbb + (long long)zh * cbh;
    int m0 = blockIdx.y * 128;
    int n0 = blockIdx.x * NT;

    float acc[MT][8][4];
#pragma unroll
    for (int mt = 0; mt < MT; mt++)
#pragma unroll
        for (int nt = 0; nt < 8; nt++)
#pragma unroll
            for (int q = 0; q < 4; q++) acc[mt][nt][q] = 0.f;

    int kchunks = K >> 5;
    int nch = npairs * kchunks;

    // ---- async stage: issue chunk cc into buffer cc&1 ----
    auto issue = [&](int cc) {
        int p = cc / kchunks;
        int k0 = (cc - p * kchunks) << 5;
        int buf = cc & 1;
        const float* Ab = (p == 0 ? a0p : (p == 1 ? a1p : a2p));
        const float* Bb = (p == 0 ? b0p : (p == 1 ? b1p : b2p));
        const float* Ap = Ab + aoff + (size_t)m0 * lda + k0;
        uint32_t abase = a_u32 + buf * ASTG * 4;
#pragma unroll
        for (int t = 0; t < 4; t++) {
            int i = tid + t * 256;
            int r = i >> 3, f = i & 7;
            cpa16(abase + (uint32_t)(r * ASTRIDE + f * 4) * 4,
                  Ap + (size_t)r * lda + f * 4);
        }
        uint32_t bbase = b_u32 + buf * BSTG * 4;
        if (BT == 0) {
            const float* Bp = Bb + boff + (size_t)n0 * ldb + k0;
#pragma unroll
            for (int t = 0; t < NT / 32; t++) {
                int i = tid + t * 256;
                int r = i >> 3, f = i & 7;
                cpa16(bbase + (uint32_t)(r * BSTRIDE + f * 4) * 4,
                      Bp + (size_t)r * ldb + f * 4);
            }
        } else {
            const float* Bp = Bb + boff + (size_t)k0 * ldb + n0;
#pragma unroll
            for (int t = 0; t < NT / 32; t++) {
                int i = tid + t * 256;
                int k = i / (NT / 4), q = i % (NT / 4);
                cpa16(bbase + (uint32_t)(k * BSTRIDE + q * 4) * 4,
                      Bp + (size_t)k * ldb + q * 4);
            }
        }
    };

    issue(0);
    CP_COMMIT();

    for (int c = 0; c < nch; c++) {
        if (c + 1 < nch) {
            issue(c + 1);
            CP_COMMIT();
            CP_WAIT1();
        } else {
            CP_WAIT0();
        }
        __syncthreads();

        int buf = c & 1;
        const float* Ablk = Asf + buf * ASTG;
        const float* Bblk = Bsf + buf * BSTG;

        // per-chunk A-bias (bias_pf) values for this thread's gc lanes
        float bk[4][2];
        if (abias) {
            int p = c / kchunks;
            int k0 = (c - p * kchunks) << 5;
            const float* ab = abias + zh * DH_ + k0;
#pragma unroll
            for (int ks = 0; ks < 4; ks++) {
                bk[ks][0] = ab[ks * 8 + gc];
                bk[ks][1] = ab[ks * 8 + gc + 4];
            }
        } else {
#pragma unroll
            for (int ks = 0; ks < 4; ks++) { bk[ks][0] = 0.f; bk[ks][1] = 0.f; }
        }

#pragma unroll
        for (int ks = 0; ks < 4; ks++) {
            int k = ks * 8;
            uint32_t af[MT][4];
#pragma unroll
            for (int mt = 0; mt < MT; mt++) {
                int row = wm + mt * 16 + gr;
                af[mt][0] = f2tf32(Ablk[row * ASTRIDE + k + gc] + bk[ks][0]);
                af[mt][1] = f2tf32(Ablk[(row + 8) * ASTRIDE + k + gc] + bk[ks][0]);
                af[mt][2] = f2tf32(Ablk[row * ASTRIDE + k + gc + 4] + bk[ks][1]);
                af[mt][3] = f2tf32(Ablk[(row + 8) * ASTRIDE + k + gc + 4] + bk[ks][1]);
            }
#pragma unroll
            for (int nt = 0; nt < 8; nt++) {
                int col = wn0 + nt * 8 + gr;
                uint32_t b0, b1;
                if (BT == 0) {
                    b0 = f2tf32(Bblk[col * BSTRIDE + k + gc]);
                    b1 = f2tf32(Bblk[col * BSTRIDE + k + gc + 4]);
                } else {
                    b0 = f2tf32(Bblk[(k + gc) * BSTRIDE + col]);
                    b1 = f2tf32(Bblk[(k + gc + 4) * BSTRIDE + col]);
                }
#pragma unroll
                for (int mt = 0; mt < MT; mt++)
                    mma_tf32(acc[mt][nt][0], acc[mt][nt][1], acc[mt][nt][2], acc[mt][nt][3],
                             af[mt][0], af[mt][1], af[mt][2], af[mt][3], b0, b1);
            }
        }
        __syncthreads();
    }

    // ---- epilogue ----
    float* Cp = C + coff;
    const float* Rp = resid ? (resid + coff) : (const float*)0;
#pragma unroll
    for (int mt = 0; mt < MT; mt++) {
#pragma unroll
        for (int half = 0; half < 2; half++) {
            int rr = m0 + wm + mt * 16 + gr + half * 8;
#pragma unroll
            for (int nt = 0; nt < 8; nt++) {
                int cc = n0 + wn0 + nt * 8 + 2 * gc;
                float v0 = acc[mt][nt][half * 2 + 0];
                float v1 = acc[mt][nt][half * 2 + 1];
                size_t o = (size_t)rr * ldc + cc;
                if (flags & 1) { v0 += bias[cc]; v1 += bias[cc + 1]; }
                if (flags & 2) { v0 += Rp[o]; v1 += Rp[o + 1]; }
                if (flags & 4) {
                    v0 = 0.5f * v0 * (1.0f + erff(v0 * 0.70710678118654752f));
                    v1 = 0.5f * v1 * (1.0f + erff(v1 * 0.70710678118654752f));
                }
                float2 w = { v0, v1 };
                *(float2*)(Cp + o) = w;
            }
        }
    }
}

// smem byte sizes per instantiation
#define SMEM_128_0 ((2 * 128 * 36 + 2 * 128 * 36) * 4)
#define SMEM_128_1 ((2 * 128 * 36 + 2 * 32 * 136) * 4)
#define SMEM_64_1  ((2 * 128 * 36 + 2 * 32 * 72) * 4)

// ---------------------------------------------------------------------------
// LayerNorm: one block (256 threads) per row of D_=512
// ---------------------------------------------------------------------------
__global__ void ln_kernel(const float* __restrict__ x,
                          const float* __restrict__ g,
                          const float* __restrict__ b,
                          float* __restrict__ out) {
    int row = blockIdx.x;
    int t = threadIdx.x;
    const float* xr = x + (size_t)row * D_;
    __shared__ float red[256];

    float v0 = xr[t];
    float v1 = xr[t + 256];
    red[t] = v0 + v1;
    __syncthreads();
    for (int o = 128; o > 0; o >>= 1) { if (t < o) red[t] += red[t + o]; __syncthreads(); }
    float mean = red[0] * (1.0f / D_);
    __syncthreads();

    float d0 = v0 - mean, d1 = v1 - mean;
    red[t] = d0 * d0 + d1 * d1;
    __syncthreads();
    for (int o = 128; o > 0; o >>= 1) { if (t < o) red[t] += red[t + o]; __syncthreads(); }
    float inv = rsqrtf(red[0] * (1.0f / D_) + 1e-5f);

    out[(size_t)row * D_ + t]       = d0 * inv * g[t]       + b[t];
    out[(size_t)row * D_ + t + 256] = d1 * inv * g[t + 256] + b[t + 256];
}

// ---------------------------------------------------------------------------
// Fused rel_shift gather + softmax over heads (axis=-1 is h!)
//   j <= i   : S[i, N-1-i+j];  j == i+1 : 0;  j > i+1 : S[i+1, j-i-2]
// ---------------------------------------------------------------------------
__global__ void softmax_shift_kernel(const float* __restrict__ AC,
                                     const float* __restrict__ S,
                                     float* __restrict__ attn) {
    int t = blockIdx.x * blockDim.x + threadIdx.x;
    if (t >= B_ * N_ * N_) return;
    int j = t & (N_ - 1);
    int i = (t >> 10) & (N_ - 1);
    int b = t >> 20;

    float vals[H_];
    float mx = -1e30f;
#pragma unroll
    for (int h = 0; h < H_; h++) {
        size_t base = (size_t)(b * H_ + h) * N_;
        float ac = AC[(base + i) * N_ + j];
        float s;
        if (j <= i)           s = S[(base + i) * N_ + (N_ - 1 - i + j)];
        else if (j == i + 1)  s = 0.f;
        else                  s = S[(base + i + 1) * N_ + (j - i - 2)];
        float v = (ac + s * (1.0f / 3.0f)) * SCALE_;
        vals[h] = v;
        mx = fmaxf(mx, v);
    }
    float sum = 0.f;
#pragma unroll
    for (int h = 0; h < H_; h++) { vals[h] = expf(vals[h] - mx); sum += vals[h]; }
    float inv = 1.0f / sum;
#pragma unroll
    for (int h = 0; h < H_; h++)
        attn[((size_t)(b * H_ + h) * N_ + i) * N_ + j] = vals[h] * inv;
}

// ---------------------------------------------------------------------------
// Host-side orchestration
// ---------------------------------------------------------------------------
extern "C" void kernel_launch(void* const* d_in, const int* in_sizes, int n_in,
                              void* d_out, int out_size) {
    (void)in_sizes; (void)n_in; (void)out_size;
    const float* x       = (const float*)d_in[0];
    const float* r_t     = (const float*)d_in[1];
    const float* r_c     = (const float*)d_in[2];
    const float* r_p     = (const float*)d_in[3];
    const float* bias_pf = (const float*)d_in[4];
    const float* ln1_g   = (const float*)d_in[5];
    const float* ln1_b   = (const float*)d_in[6];
    const float* w_qkv   = (const float*)d_in[7];
    const float* w_out   = (const float*)d_in[8];
    const float* b_out   = (const float*)d_in[9];
    const float* w_kt    = (const float*)d_in[10];
    const float* w_kc    = (const float*)d_in[11];
    const float* w_kp    = (const float*)d_in[12];
    const float* ln2_g   = (const float*)d_in[13];
    const float* ln2_b   = (const float*)d_in[14];
    const float* w_ff1   = (const float*)d_in[15];
    const float* b_ff1   = (const float*)d_in[16];
    const float* w_ff2   = (const float*)d_in[17];
    const float* b_ff2   = (const float*)d_in[18];

    float* out      = (float*)d_out;
    float* attn_out = out + (size_t)BN_TOK * D_;

    float *xbuf, *xn, *qkv, *wsum, *AC, *S, *obh, *h1;
    cudaGetSymbolAddress((void**)&xbuf, g_xbuf);
    cudaGetSymbolAddress((void**)&xn,   g_xn);
    cudaGetSymbolAddress((void**)&qkv,  g_qkv);
    cudaGetSymbolAddress((void**)&wsum, g_wsum);
    cudaGetSymbolAddress((void**)&AC,   g_AC);
    cudaGetSymbolAddress((void**)&S,    g_S);
    cudaGetSymbolAddress((void**)&obh,  g_obh);
    cudaGetSymbolAddress((void**)&h1,   g_h1);

    static int smem_set = 0;
    if (!smem_set) {
        cudaFuncSetAttribute(mma_gemm<128,0>, cudaFuncAttributeMaxDynamicSharedMemorySize, SMEM_128_0);
        cudaFuncSetAttribute(mma_gemm<128,1>, cudaFuncAttributeMaxDynamicSharedMemorySize, SMEM_128_1);
        cudaFuncSetAttribute(mma_gemm<64,1>,  cudaFuncAttributeMaxDynamicSharedMemorySize, SMEM_64_1);
        smem_set = 1;
    }

    cudaMemcpyAsync(xbuf, x, sizeof(float) * BN_TOK * D_, cudaMemcpyDeviceToDevice);

    const long long NN = (long long)N_ * N_;
    const long long QKVB = (long long)N_ * 3 * HD_;

    for (int l = 0; l < DEPTH_; l++) {
        // ln1
        ln_kernel<<<BN_TOK, 256>>>(xbuf, ln1_g + l * D_, ln1_b + l * D_, xn);

        // qkv = xn @ w_qkv[l]           (M=2048, N=1536, K=512)
        mma_gemm<128,1><<<dim3(12, 16, 1), 256, SMEM_128_1>>>(
            xn, 0, 0, w_qkv + (size_t)l * D_ * 3 * HD_, 0, 0,
            1, D_, D_, 3 * HD_, 0, 0, 0, 0, 0,
            qkv, 3 * HD_, 0, 0, 0, 0, 0);

        // wsum = r_t@w_kt + r_c@w_kc + r_p@w_kp   (3-pair fused)
        mma_gemm<128,1><<<dim3(4, 16, 1), 256, SMEM_128_1>>>(
            r_t, r_c, r_p,
            w_kt + (size_t)l * D_ * HD_, w_kc + (size_t)l * D_ * HD_, w_kp + (size_t)l * D_ * HD_,
            3, D_, D_, HD_, 0, 0, 0, 0, 0,
            wsum, HD_, 0, 0, 0, 0, 0);

        // AC[b,h] = (q+bias_pf) @ k^T     (batched z=16, M=N=1024, K=64)
        mma_gemm<128,0><<<dim3(8, 8, 16), 256, SMEM_128_0>>>(
            qkv, 0, 0, qkv + HD_, 0, 0,
            1, DH_, 3 * HD_, 3 * HD_,
            QKVB, 64, QKVB, 64, bias_pf,
            AC, N_, 8 * NN, NN, 0, 0, 0);

        // S[b,h] = (q+bias_pf) @ wsum^T
        mma_gemm<128,0><<<dim3(8, 8, 16), 256, SMEM_128_0>>>(
            qkv, 0, 0, wsum, 0, 0,
            1, DH_, 3 * HD_, HD_,
            QKVB, 64, (long long)N_ * HD_, 64, bias_pf,
            S, N_, 8 * NN, NN, 0, 0, 0);

        // rel_shift + softmax over heads -> attn (output layout b,h,q,k)
        softmax_shift_kernel<<<(B_ * N_ * N_ + 255) / 256, 256>>>(AC, S, attn_out);

        // obh[b,i,h*64+d] = attn[b,h] @ v[b,h]   (batched z=16, M=1024, N=64, K=1024)
        mma_gemm<64,1><<<dim3(1, 8, 16), 256, SMEM_64_1>>>(
            attn_out, 0, 0, qkv + 2 * HD_, 0, 0,
            1, N_, N_, 3 * HD_,
            8 * NN, NN, QKVB, 64, 0,
            obh, HD_, (long long)N_ * HD_, 64, 0, 0, 0);

        // x = obh @ w_out + b_out + x
        mma_gemm<128,1><<<dim3(4, 16, 1), 256, SMEM_128_1>>>(
            obh, 0, 0, w_out + (size_t)l * HD_ * D_, 0, 0,
            1, HD_, HD_, D_, 0, 0, 0, 0, 0,
            xbuf, D_, 0, 0, b_out + l * D_, xbuf, 3);

        // ln2
        ln_kernel<<<BN_TOK, 256>>>(xbuf, ln2_g + l * D_, ln2_b + l * D_, xn);

        // h1 = gelu(xn @ w_ff1 + b_ff1)    (M=2048, N=2048, K=512)
        mma_gemm<128,1><<<dim3(16, 16, 1), 256, SMEM_128_1>>>(
            xn, 0, 0, w_ff1 + (size_t)l * D_ * FF_, 0, 0,
            1, D_, D_, FF_, 0, 0, 0, 0, 0,
            h1, FF_, 0, 0, b_ff1 + l * FF_, 0, 5);

        // x = h1 @ w_ff2 + b_ff2 + x       (M=2048, N=512, K=2048)
        mma_gemm<128,1><<<dim3(4, 16, 1), 256, SMEM_128_1>>>(
            h1, 0, 0, w_ff2 + (size_t)l * FF_ * D_, 0, 0,
            1, FF_, FF_, D_, 0, 0, 0, 0, 0,
            xbuf, D_, 0, 0, b_ff2 + l * D_, xbuf, 3);
    }

    cudaMemcpyAsync(out, xbuf, sizeof(float) * BN_TOK * D_, cudaMemcpyDeviceToDevice);
}

// round 11
// speedup vs baseline: 3.3407x; 1.2599x over previous
#include <cuda_runtime.h>
#include <math.h>
#include <stdint.h>

// Problem constants
#define B_    2
#define N_    1024
#define D_    512
#define H_    8
#define DH_   64
#define HD_   512
#define FF_   2048
#define DEPTH_ 4
#define BN_TOK (B_*N_)
#define SCALE_ 0.125f

// ---------------------------------------------------------------------------
// Scratch (static __device__ arrays; no allocation allowed)
// ---------------------------------------------------------------------------
__device__ float g_xbuf [BN_TOK * D_];
__device__ float g_xn   [BN_TOK * D_];
__device__ float g_qkv  [BN_TOK * 3 * HD_];
__device__ float g_wsum [BN_TOK * HD_];
__device__ float g_AC   [B_*H_*N_*N_];
__device__ float g_S    [B_*H_*N_*N_];
__device__ float g_obh  [BN_TOK * HD_];
__device__ float g_h1   [BN_TOK * FF_];

// ---------------------------------------------------------------------------
// helpers
// ---------------------------------------------------------------------------
__device__ __forceinline__ uint32_t f2tf32(float x) {
    uint32_t u;
    asm("cvt.rna.tf32.f32 %0, %1;" : "=r"(u) : "f"(x));
    return u;
}

__device__ __forceinline__ void mma_tf32(float& d0, float& d1, float& d2, float& d3,
                                         uint32_t a0, uint32_t a1, uint32_t a2, uint32_t a3,
                                         uint32_t b0, uint32_t b1) {
    asm volatile(
        "mma.sync.aligned.m16n8k8.row.col.f32.tf32.tf32.f32 "
        "{%0,%1,%2,%3}, {%4,%5,%6,%7}, {%8,%9}, {%0,%1,%2,%3};"
        : "+f"(d0), "+f"(d1), "+f"(d2), "+f"(d3)
        : "r"(a0), "r"(a1), "r"(a2), "r"(a3), "r"(b0), "r"(b1));
}

__device__ __forceinline__ void cpa16(uint32_t dst, const float* src) {
    asm volatile("cp.async.cg.shared.global [%0], [%1], 16;" :: "r"(dst), "l"(src));
}
#define CP_COMMIT() asm volatile("cp.async.commit_group;" ::: "memory")
#define CP_WAIT1()  asm volatile("cp.async.wait_group 1;" ::: "memory")
#define CP_WAIT0()  asm volatile("cp.async.wait_group 0;" ::: "memory")

// ---------------------------------------------------------------------------
// Generic warp-MMA tf32 GEMM with cp.async double-buffered pipeline + split-K.
//   C[z][m][n] = sum_p A_p[z][m][k] * B_p[z][n][k]
//   BT=0: B source K-major (N,K).  BT=1: B source (K,N) row-major.
// Block: 256 threads, tile 128 x NT, K-chunk 32.
// Split-K: gridDim.x = ntiles_x * ksplit; block handles chunk range
//   [kspl*nch/ksplit, (kspl+1)*nch/ksplit).
// flags: 1=col bias, 2=residual add, 4=exact gelu, 8=atomic accumulate
//   (atomic mode: bias applied only by kspl==0; resid ignored — C holds it).
// ---------------------------------------------------------------------------
template<int NT, int BT>
__global__ void __launch_bounds__(256, 2) mma_gemm(
    const float* a0p, const float* a1p, const float* a2p,
    const float* b0p, const float* b1p, const float* b2p,
    int npairs, int K, int lda, int ldb, int ksplit,
    long long abb, long long abh, long long bbb, long long bbh,
    const float* abias,
    float* C, int ldc, long long cbb, long long cbh,
    const float* bias, const float* resid, int flags)
{
    extern __shared__ float smem[];
    constexpr int ASTRIDE = 36;
    constexpr int ASTG = 128 * ASTRIDE;
    constexpr int BSTRIDE = (BT == 0) ? 36 : ((NT == 128) ? 136 : 72);
    constexpr int BSTG = (BT == 0) ? NT * 36 : 32 * BSTRIDE;

    float* Asf = smem;
    float* Bsf = smem + 2 * ASTG;
    uint32_t smem_u32 = (uint32_t)__cvta_generic_to_shared(smem);
    uint32_t a_u32 = smem_u32;
    uint32_t b_u32 = smem_u32 + 2 * ASTG * 4;

    constexpr int MT = (NT == 128) ? 2 : 1;
    int tid = threadIdx.x;
    int warp = tid >> 5, lane = tid & 31;
    int gr = lane >> 2, gc = lane & 3;

    int wm  = (NT == 128) ? (warp & 3) * 32 : warp * 16;
    int wn0 = (NT == 128) ? (warp >> 2) * 64 : 0;

    int ntx = gridDim.x / ksplit;
    int nti = blockIdx.x % ntx;
    int kspl = blockIdx.x / ntx;

    int zb = blockIdx.z >> 3, zh = blockIdx.z & 7;
    long long aoff = (long long)zb * abb + (long long)zh * abh;
    long long boff = (long long)zb * bbb + (long long)zh * bbh;
    long long coff = (long long)zb * cbb + (long long)zh * cbh;
    int m0 = blockIdx.y * 128;
    int n0 = nti * NT;

    float acc[MT][8][4];
#pragma unroll
    for (int mt = 0; mt < MT; mt++)
#pragma unroll
        for (int nt = 0; nt < 8; nt++)
#pragma unroll
            for (int q = 0; q < 4; q++) acc[mt][nt][q] = 0.f;

    int kchunks = K >> 5;
    int nch = npairs * kchunks;
    int c0 = (nch * kspl) / ksplit;
    int c1 = (nch * (kspl + 1)) / ksplit;

    auto issue = [&](int cc) {
        int p = cc / kchunks;
        int k0 = (cc - p * kchunks) << 5;
        int buf = cc & 1;
        const float* Ab = (p == 0 ? a0p : (p == 1 ? a1p : a2p));
        const float* Bb = (p == 0 ? b0p : (p == 1 ? b1p : b2p));
        const float* Ap = Ab + aoff + (size_t)m0 * lda + k0;
        uint32_t abase = a_u32 + buf * ASTG * 4;
#pragma unroll
        for (int t = 0; t < 4; t++) {
            int i = tid + t * 256;
            int r = i >> 3, f = i & 7;
            cpa16(abase + (uint32_t)(r * ASTRIDE + f * 4) * 4,
                  Ap + (size_t)r * lda + f * 4);
        }
        uint32_t bbase = b_u32 + buf * BSTG * 4;
        if (BT == 0) {
            const float* Bp = Bb + boff + (size_t)n0 * ldb + k0;
#pragma unroll
            for (int t = 0; t < NT / 32; t++) {
                int i = tid + t * 256;
                int r = i >> 3, f = i & 7;
                cpa16(bbase + (uint32_t)(r * BSTRIDE + f * 4) * 4,
                      Bp + (size_t)r * ldb + f * 4);
            }
        } else {
            const float* Bp = Bb + boff + (size_t)k0 * ldb + n0;
#pragma unroll
            for (int t = 0; t < NT / 32; t++) {
                int i = tid + t * 256;
                int k = i / (NT / 4), q = i % (NT / 4);
                cpa16(bbase + (uint32_t)(k * BSTRIDE + q * 4) * 4,
                      Bp + (size_t)k * ldb + q * 4);
            }
        }
    };

    issue(c0);
    CP_COMMIT();

    for (int c = c0; c < c1; c++) {
        if (c + 1 < c1) {
            issue(c + 1);
            CP_COMMIT();
            CP_WAIT1();
        } else {
            CP_WAIT0();
        }
        __syncthreads();

        int buf = c & 1;
        const float* Ablk = Asf + buf * ASTG;
        const float* Bblk = Bsf + buf * BSTG;

        float bk[4][2];
        if (abias) {
            int p = c / kchunks;
            int k0 = (c - p * kchunks) << 5;
            const float* ab = abias + zh * DH_ + k0;
#pragma unroll
            for (int ks = 0; ks < 4; ks++) {
                bk[ks][0] = ab[ks * 8 + gc];
                bk[ks][1] = ab[ks * 8 + gc + 4];
            }
        } else {
#pragma unroll
            for (int ks = 0; ks < 4; ks++) { bk[ks][0] = 0.f; bk[ks][1] = 0.f; }
        }

#pragma unroll
        for (int ks = 0; ks < 4; ks++) {
            int k = ks * 8;
            uint32_t af[MT][4];
#pragma unroll
            for (int mt = 0; mt < MT; mt++) {
                int row = wm + mt * 16 + gr;
                af[mt][0] = f2tf32(Ablk[row * ASTRIDE + k + gc] + bk[ks][0]);
                af[mt][1] = f2tf32(Ablk[(row + 8) * ASTRIDE + k + gc] + bk[ks][0]);
                af[mt][2] = f2tf32(Ablk[row * ASTRIDE + k + gc + 4] + bk[ks][1]);
                af[mt][3] = f2tf32(Ablk[(row + 8) * ASTRIDE + k + gc + 4] + bk[ks][1]);
            }
#pragma unroll
            for (int nt = 0; nt < 8; nt++) {
                int col = wn0 + nt * 8 + gr;
                uint32_t b0, b1;
                if (BT == 0) {
                    b0 = f2tf32(Bblk[col * BSTRIDE + k + gc]);
                    b1 = f2tf32(Bblk[col * BSTRIDE + k + gc + 4]);
                } else {
                    b0 = f2tf32(Bblk[(k + gc) * BSTRIDE + col]);
                    b1 = f2tf32(Bblk[(k + gc + 4) * BSTRIDE + col]);
                }
#pragma unroll
                for (int mt = 0; mt < MT; mt++)
                    mma_tf32(acc[mt][nt][0], acc[mt][nt][1], acc[mt][nt][2], acc[mt][nt][3],
                             af[mt][0], af[mt][1], af[mt][2], af[mt][3], b0, b1);
            }
        }
        __syncthreads();
    }

    // ---- epilogue ----
    float* Cp = C + coff;
    const float* Rp = resid ? (resid + coff) : (const float*)0;
    bool atom = (flags & 8) != 0;
    bool addb = (flags & 1) && (!atom || kspl == 0);
#pragma unroll
    for (int mt = 0; mt < MT; mt++) {
#pragma unroll
        for (int half = 0; half < 2; half++) {
            int rr = m0 + wm + mt * 16 + gr + half * 8;
#pragma unroll
            for (int nt = 0; nt < 8; nt++) {
                int cc = n0 + wn0 + nt * 8 + 2 * gc;
                float v0 = acc[mt][nt][half * 2 + 0];
                float v1 = acc[mt][nt][half * 2 + 1];
                size_t o = (size_t)rr * ldc + cc;
                if (addb) { v0 += bias[cc]; v1 += bias[cc + 1]; }
                if (atom) {
                    atomicAdd(Cp + o, v0);
                    atomicAdd(Cp + o + 1, v1);
                } else {
                    if (flags & 2) { v0 += Rp[o]; v1 += Rp[o + 1]; }
                    if (flags & 4) {
                        v0 = 0.5f * v0 * (1.0f + erff(v0 * 0.70710678118654752f));
                        v1 = 0.5f * v1 * (1.0f + erff(v1 * 0.70710678118654752f));
                    }
                    float2 w = { v0, v1 };
                    *(float2*)(Cp + o) = w;
                }
            }
        }
    }
}

// smem byte sizes per instantiation
#define SMEM_128_0 ((2 * 128 * 36 + 2 * 128 * 36) * 4)
#define SMEM_128_1 ((2 * 128 * 36 + 2 * 32 * 136) * 4)
#define SMEM_64_1  ((2 * 128 * 36 + 2 * 32 * 72) * 4)

// ---------------------------------------------------------------------------
// LayerNorm: one block (256 threads) per row of D_=512
// ---------------------------------------------------------------------------
__global__ void ln_kernel(const float* __restrict__ x,
                          const float* __restrict__ g,
                          const float* __restrict__ b,
                          float* __restrict__ out) {
    int row = blockIdx.x;
    int t = threadIdx.x;
    const float* xr = x + (size_t)row * D_;
    __shared__ float red[256];

    float v0 = xr[t];
    float v1 = xr[t + 256];
    red[t] = v0 + v1;
    __syncthreads();
    for (int o = 128; o > 0; o >>= 1) { if (t < o) red[t] += red[t + o]; __syncthreads(); }
    float mean = red[0] * (1.0f / D_);
    __syncthreads();

    float d0 = v0 - mean, d1 = v1 - mean;
    red[t] = d0 * d0 + d1 * d1;
    __syncthreads();
    for (int o = 128; o > 0; o >>= 1) { if (t < o) red[t] += red[t + o]; __syncthreads(); }
    float inv = rsqrtf(red[0] * (1.0f / D_) + 1e-5f);

    out[(size_t)row * D_ + t]       = d0 * inv * g[t]       + b[t];
    out[(size_t)row * D_ + t + 256] = d1 * inv * g[t + 256] + b[t + 256];
}

// ---------------------------------------------------------------------------
// Fused rel_shift gather + softmax over heads (axis=-1 is h!)
//   j <= i   : S[i, N-1-i+j];  j == i+1 : 0;  j > i+1 : S[i+1, j-i-2]
// ---------------------------------------------------------------------------
__global__ void softmax_shift_kernel(const float* __restrict__ AC,
                                     const float* __restrict__ S,
                                     float* __restrict__ attn) {
    int t = blockIdx.x * blockDim.x + threadIdx.x;
    if (t >= B_ * N_ * N_) return;
    int j = t & (N_ - 1);
    int i = (t >> 10) & (N_ - 1);
    int b = t >> 20;

    float vals[H_];
    float mx = -1e30f;
#pragma unroll
    for (int h = 0; h < H_; h++) {
        size_t base = (size_t)(b * H_ + h) * N_;
        float ac = AC[(base + i) * N_ + j];
        float s;
        if (j <= i)           s = S[(base + i) * N_ + (N_ - 1 - i + j)];
        else if (j == i + 1)  s = 0.f;
        else                  s = S[(base + i + 1) * N_ + (j - i - 2)];
        float v = (ac + s * (1.0f / 3.0f)) * SCALE_;
        vals[h] = v;
        mx = fmaxf(mx, v);
    }
    float sum = 0.f;
#pragma unroll
    for (int h = 0; h < H_; h++) { vals[h] = expf(vals[h] - mx); sum += vals[h]; }
    float inv = 1.0f / sum;
#pragma unroll
    for (int h = 0; h < H_; h++)
        attn[((size_t)(b * H_ + h) * N_ + i) * N_ + j] = vals[h] * inv;
}

// ---------------------------------------------------------------------------
// Host-side orchestration
// ---------------------------------------------------------------------------
extern "C" void kernel_launch(void* const* d_in, const int* in_sizes, int n_in,
                              void* d_out, int out_size) {
    (void)in_sizes; (void)n_in; (void)out_size;
    const float* x       = (const float*)d_in[0];
    const float* r_t     = (const float*)d_in[1];
    const float* r_c     = (const float*)d_in[2];
    const float* r_p     = (const float*)d_in[3];
    const float* bias_pf = (const float*)d_in[4];
    const float* ln1_g   = (const float*)d_in[5];
    const float* ln1_b   = (const float*)d_in[6];
    const float* w_qkv   = (const float*)d_in[7];
    const float* w_out   = (const float*)d_in[8];
    const float* b_out   = (const float*)d_in[9];
    const float* w_kt    = (const float*)d_in[10];
    const float* w_kc    = (const float*)d_in[11];
    const float* w_kp    = (const float*)d_in[12];
    const float* ln2_g   = (const float*)d_in[13];
    const float* ln2_b   = (const float*)d_in[14];
    const float* w_ff1   = (const float*)d_in[15];
    const float* b_ff1   = (const float*)d_in[16];
    const float* w_ff2   = (const float*)d_in[17];
    const float* b_ff2   = (const float*)d_in[18];

    float* out      = (float*)d_out;
    float* attn_out = out + (size_t)BN_TOK * D_;

    float *xbuf, *xn, *qkv, *wsum, *AC, *S, *obh, *h1;
    cudaGetSymbolAddress((void**)&xbuf, g_xbuf);
    cudaGetSymbolAddress((void**)&xn,   g_xn);
    cudaGetSymbolAddress((void**)&qkv,  g_qkv);
    cudaGetSymbolAddress((void**)&wsum, g_wsum);
    cudaGetSymbolAddress((void**)&AC,   g_AC);
    cudaGetSymbolAddress((void**)&S,    g_S);
    cudaGetSymbolAddress((void**)&obh,  g_obh);
    cudaGetSymbolAddress((void**)&h1,   g_h1);

    static int smem_set = 0;
    if (!smem_set) {
        cudaFuncSetAttribute(mma_gemm<128,0>, cudaFuncAttributeMaxDynamicSharedMemorySize, SMEM_128_0);
        cudaFuncSetAttribute(mma_gemm<128,1>, cudaFuncAttributeMaxDynamicSharedMemorySize, SMEM_128_1);
        cudaFuncSetAttribute(mma_gemm<64,1>,  cudaFuncAttributeMaxDynamicSharedMemorySize, SMEM_64_1);
        smem_set = 1;
    }

    cudaMemcpyAsync(xbuf, x, sizeof(float) * BN_TOK * D_, cudaMemcpyDeviceToDevice);

    const long long NN = (long long)N_ * N_;
    const long long QKVB = (long long)N_ * 3 * HD_;

    for (int l = 0; l < DEPTH_; l++) {
        // ln1
        ln_kernel<<<BN_TOK, 256>>>(xbuf, ln1_g + l * D_, ln1_b + l * D_, xn);

        // qkv = xn @ w_qkv[l]           (M=2048, N=1536, K=512)
        mma_gemm<128,1><<<dim3(12, 16, 1), 256, SMEM_128_1>>>(
            xn, 0, 0, w_qkv + (size_t)l * D_ * 3 * HD_, 0, 0,
            1, D_, D_, 3 * HD_, 1, 0, 0, 0, 0, 0,
            qkv, 3 * HD_, 0, 0, 0, 0, 0);

        // wsum = r_t@w_kt + r_c@w_kc + r_p@w_kp   (3-pair fused, split-K x4)
        cudaMemsetAsync(wsum, 0, sizeof(float) * BN_TOK * HD_);
        mma_gemm<128,1><<<dim3(16, 16, 1), 256, SMEM_128_1>>>(
            r_t, r_c, r_p,
            w_kt + (size_t)l * D_ * HD_, w_kc + (size_t)l * D_ * HD_, w_kp + (size_t)l * D_ * HD_,
            3, D_, D_, HD_, 4, 0, 0, 0, 0, 0,
            wsum, HD_, 0, 0, 0, 0, 8);

        // AC[b,h] = (q+bias_pf) @ k^T     (batched z=16, M=N=1024, K=64)
        mma_gemm<128,0><<<dim3(8, 8, 16), 256, SMEM_128_0>>>(
            qkv, 0, 0, qkv + HD_, 0, 0,
            1, DH_, 3 * HD_, 3 * HD_, 1,
            QKVB, 64, QKVB, 64, bias_pf,
            AC, N_, 8 * NN, NN, 0, 0, 0);

        // S[b,h] = (q+bias_pf) @ wsum^T
        mma_gemm<128,0><<<dim3(8, 8, 16), 256, SMEM_128_0>>>(
            qkv, 0, 0, wsum, 0, 0,
            1, DH_, 3 * HD_, HD_, 1,
            QKVB, 64, (long long)N_ * HD_, 64, bias_pf,
            S, N_, 8 * NN, NN, 0, 0, 0);

        // rel_shift + softmax over heads -> attn (output layout b,h,q,k)
        softmax_shift_kernel<<<(B_ * N_ * N_ + 255) / 256, 256>>>(AC, S, attn_out);

        // obh = attn @ v   (batched z=16, M=1024, N=64, K=1024, split-K x4)
        cudaMemsetAsync(obh, 0, sizeof(float) * BN_TOK * HD_);
        mma_gemm<64,1><<<dim3(4, 8, 16), 256, SMEM_64_1>>>(
            attn_out, 0, 0, qkv + 2 * HD_, 0, 0,
            1, N_, N_, 3 * HD_, 4,
            8 * NN, NN, QKVB, 64, 0,
            obh, HD_, (long long)N_ * HD_, 64, 0, 0, 8);

        // x += obh @ w_out + b_out   (split-K x4, xbuf already holds x)
        mma_gemm<128,1><<<dim3(16, 16, 1), 256, SMEM_128_1>>>(
            obh, 0, 0, w_out + (size_t)l * HD_ * D_, 0, 0,
            1, HD_, HD_, D_, 4, 0, 0, 0, 0, 0,
            xbuf, D_, 0, 0, b_out + l * D_, 0, 9);

        // ln2
        ln_kernel<<<BN_TOK, 256>>>(xbuf, ln2_g + l * D_, ln2_b + l * D_, xn);

        // h1 = gelu(xn @ w_ff1 + b_ff1)    (M=2048, N=2048, K=512)
        mma_gemm<128,1><<<dim3(16, 16, 1), 256, SMEM_128_1>>>(
            xn, 0, 0, w_ff1 + (size_t)l * D_ * FF_, 0, 0,
            1, D_, D_, FF_, 1, 0, 0, 0, 0, 0,
            h1, FF_, 0, 0, b_ff1 + l * FF_, 0, 5);

        // x += h1 @ w_ff2 + b_ff2   (M=2048, N=512, K=2048, split-K x4)
        mma_gemm<128,1><<<dim3(16, 16, 1), 256, SMEM_128_1>>>(
            h1, 0, 0, w_ff2 + (size_t)l * FF_ * D_, 0, 0,
            1, FF_, FF_, D_, 4, 0, 0, 0, 0, 0,
            xbuf, D_, 0, 0, b_ff2 + l * D_, 0, 9);
    }

    cudaMemcpyAsync(out, xbuf, sizeof(float) * BN_TOK * D_, cudaMemcpyDeviceToDevice);
}

// round 12
// speedup vs baseline: 3.6249x; 1.0851x over previous
#include <cuda_runtime.h>
#include <math.h>
#include <stdint.h>

// Problem constants
#define B_    2
#define N_    1024
#define D_    512
#define H_    8
#define DH_   64
#define HD_   512
#define FF_   2048
#define DEPTH_ 4
#define BN_TOK (B_*N_)
#define SCALE_ 0.125f

// ---------------------------------------------------------------------------
// Scratch (static __device__ arrays; no allocation allowed)
// ---------------------------------------------------------------------------
__device__ float g_xbuf [BN_TOK * D_];
__device__ float g_xn   [BN_TOK * D_];
__device__ float g_qkv  [BN_TOK * 3 * HD_];
__device__ float g_wsum [BN_TOK * HD_];
__device__ float g_AC   [B_*H_*N_*N_];
__device__ float g_S    [B_*H_*N_*N_];
__device__ float g_obh  [BN_TOK * HD_];
__device__ float g_h1   [BN_TOK * FF_];

// ---------------------------------------------------------------------------
// helpers
// ---------------------------------------------------------------------------
__device__ __forceinline__ uint32_t f2tf32(float x) {
    uint32_t u;
    asm("cvt.rna.tf32.f32 %0, %1;" : "=r"(u) : "f"(x));
    return u;
}
__device__ __forceinline__ float roundtf(float x) {
    return __uint_as_float(f2tf32(x));
}

__device__ __forceinline__ void mma_tf32(float& d0, float& d1, float& d2, float& d3,
                                         uint32_t a0, uint32_t a1, uint32_t a2, uint32_t a3,
                                         uint32_t b0, uint32_t b1) {
    asm volatile(
        "mma.sync.aligned.m16n8k8.row.col.f32.tf32.tf32.f32 "
        "{%0,%1,%2,%3}, {%4,%5,%6,%7}, {%8,%9}, {%0,%1,%2,%3};"
        : "+f"(d0), "+f"(d1), "+f"(d2), "+f"(d3)
        : "r"(a0), "r"(a1), "r"(a2), "r"(a3), "r"(b0), "r"(b1));
}

__device__ __forceinline__ void ldm_x4(uint32_t& r0, uint32_t& r1, uint32_t& r2, uint32_t& r3,
                                       uint32_t addr) {
    asm volatile("ldmatrix.sync.aligned.m8n8.x4.shared.b16 {%0,%1,%2,%3}, [%4];"
                 : "=r"(r0), "=r"(r1), "=r"(r2), "=r"(r3) : "r"(addr));
}

__device__ __forceinline__ void cpa16(uint32_t dst, const float* src) {
    asm volatile("cp.async.cg.shared.global [%0], [%1], 16;" :: "r"(dst), "l"(src));
}
#define CP_COMMIT() asm volatile("cp.async.commit_group;" ::: "memory")
#define CP_WAIT1()  asm volatile("cp.async.wait_group 1;" ::: "memory")
#define CP_WAIT0()  asm volatile("cp.async.wait_group 0;" ::: "memory")

// ---------------------------------------------------------------------------
// Generic warp-MMA tf32 GEMM, cp.async double-buffered, split-K, ldmatrix frags.
//   C[z][m][n] = sum_p A_p[z][m][k] * B_p[z][n][k]
//   BT=0: B source K-major (N,K), fragments via ldmatrix.
//   BT=1: B source (K,N) row-major, scalar fragment loads.
//   ACVT/BCVT: convert operand to tf32 at fragment time (0 = operand already
//   tf32-rounded bits in memory).
// flags: 1=col bias, 2=residual, 4=gelu, 8=atomic accumulate,
//        16=round output to tf32, 32=bias only for cols<512 (bias_pf fold).
// ---------------------------------------------------------------------------
template<int NT, int BT, int ACVT, int BCVT>
__global__ void __launch_bounds__(256, 2) mma_gemm(
    const float* a0p, const float* a1p, const float* a2p,
    const float* b0p, const float* b1p, const float* b2p,
    int npairs, int K, int lda, int ldb, int ksplit,
    long long abb, long long abh, long long bbb, long long bbh,
    float* C, int ldc, long long cbb, long long cbh,
    const float* bias, const float* resid, int flags)
{
    extern __shared__ float smem[];
    constexpr int ASTRIDE = 36;
    constexpr int ASTG = 128 * ASTRIDE;
    constexpr int BSTRIDE = (BT == 0) ? 36 : ((NT == 128) ? 136 : 72);
    constexpr int BSTG = (BT == 0) ? NT * 36 : 32 * BSTRIDE;

    float* Bsf = smem + 2 * ASTG;
    uint32_t smem_u32 = (uint32_t)__cvta_generic_to_shared(smem);
    uint32_t a_u32 = smem_u32;
    uint32_t b_u32 = smem_u32 + 2 * ASTG * 4;

    constexpr int MT = (NT == 128) ? 2 : 1;
    int tid = threadIdx.x;
    int warp = tid >> 5, lane = tid & 31;
    int gr = lane >> 2, gc = lane & 3;

    int wm  = (NT == 128) ? (warp & 3) * 32 : warp * 16;
    int wn0 = (NT == 128) ? (warp >> 2) * 64 : 0;

    int ntx = gridDim.x / ksplit;
    int nti = blockIdx.x % ntx;
    int kspl = blockIdx.x / ntx;

    int zb = blockIdx.z >> 3, zh = blockIdx.z & 7;
    long long aoff = (long long)zb * abb + (long long)zh * abh;
    long long boff = (long long)zb * bbb + (long long)zh * bbh;
    long long coff = (long long)zb * cbb + (long long)zh * cbh;
    int m0 = blockIdx.y * 128;
    int n0 = nti * NT;

    float acc[MT][8][4];
#pragma unroll
    for (int mt = 0; mt < MT; mt++)
#pragma unroll
        for (int nt = 0; nt < 8; nt++)
#pragma unroll
            for (int q = 0; q < 4; q++) acc[mt][nt][q] = 0.f;

    int kchunks = K >> 5;
    int nch = npairs * kchunks;
    int c0 = (nch * kspl) / ksplit;
    int c1 = (nch * (kspl + 1)) / ksplit;

    auto issue = [&](int cc) {
        int p = cc / kchunks;
        int k0 = (cc - p * kchunks) << 5;
        int buf = cc & 1;
        const float* Ab = (p == 0 ? a0p : (p == 1 ? a1p : a2p));
        const float* Bb = (p == 0 ? b0p : (p == 1 ? b1p : b2p));
        const float* Ap = Ab + aoff + (size_t)m0 * lda + k0;
        uint32_t abase = a_u32 + buf * ASTG * 4;
#pragma unroll
        for (int t = 0; t < 4; t++) {
            int i = tid + t * 256;
            int r = i >> 3, f = i & 7;
            cpa16(abase + (uint32_t)(r * ASTRIDE + f * 4) * 4,
                  Ap + (size_t)r * lda + f * 4);
        }
        uint32_t bbase = b_u32 + buf * BSTG * 4;
        if (BT == 0) {
            const float* Bp = Bb + boff + (size_t)n0 * ldb + k0;
#pragma unroll
            for (int t = 0; t < NT / 32; t++) {
                int i = tid + t * 256;
                int r = i >> 3, f = i & 7;
                cpa16(bbase + (uint32_t)(r * BSTRIDE + f * 4) * 4,
                      Bp + (size_t)r * ldb + f * 4);
            }
        } else {
            const float* Bp = Bb + boff + (size_t)k0 * ldb + n0;
#pragma unroll
            for (int t = 0; t < NT / 32; t++) {
                int i = tid + t * 256;
                int k = i / (NT / 4), q = i % (NT / 4);
                cpa16(bbase + (uint32_t)(k * BSTRIDE + q * 4) * 4,
                      Bp + (size_t)k * ldb + q * 4);
            }
        }
    };

    issue(c0);
    CP_COMMIT();

    for (int c = c0; c < c1; c++) {
        if (c + 1 < c1) {
            issue(c + 1);
            CP_COMMIT();
            CP_WAIT1();
        } else {
            CP_WAIT0();
        }
        __syncthreads();

        int buf = c & 1;
        uint32_t abase = a_u32 + buf * ASTG * 4;
        uint32_t bbase = b_u32 + buf * BSTG * 4;
        const float* Bblk = Bsf + buf * BSTG;

#pragma unroll
        for (int ks = 0; ks < 4; ks++) {
            int k = ks * 8;
            // ---- A fragments via ldmatrix ----
            uint32_t af[MT][4];
#pragma unroll
            for (int mt = 0; mt < MT; mt++) {
                uint32_t addr = abase +
                    (uint32_t)((wm + mt * 16 + (lane & 15)) * ASTRIDE + k + 4 * (lane >> 4)) * 4;
                ldm_x4(af[mt][0], af[mt][1], af[mt][2], af[mt][3], addr);
                if (ACVT) {
#pragma unroll
                    for (int q = 0; q < 4; q++)
                        af[mt][q] = f2tf32(__uint_as_float(af[mt][q]));
                }
            }
            // ---- B fragments ----
            uint32_t bf[8][2];
            if (BT == 0) {
#pragma unroll
                for (int np = 0; np < 4; np++) {
                    uint32_t addr = bbase +
                        (uint32_t)((wn0 + np * 16 + ((lane >> 4) << 3) + (lane & 7)) * BSTRIDE
                                   + k + ((lane >> 3) & 1) * 4) * 4;
                    ldm_x4(bf[2 * np][0], bf[2 * np][1], bf[2 * np + 1][0], bf[2 * np + 1][1], addr);
                }
                if (BCVT) {
#pragma unroll
                    for (int nt = 0; nt < 8; nt++) {
                        bf[nt][0] = f2tf32(__uint_as_float(bf[nt][0]));
                        bf[nt][1] = f2tf32(__uint_as_float(bf[nt][1]));
                    }
                }
            } else {
#pragma unroll
                for (int nt = 0; nt < 8; nt++) {
                    int col = wn0 + nt * 8 + gr;
                    float v0 = Bblk[(k + gc) * BSTRIDE + col];
                    float v1 = Bblk[(k + gc + 4) * BSTRIDE + col];
                    bf[nt][0] = BCVT ? f2tf32(v0) : __float_as_uint(v0);
                    bf[nt][1] = BCVT ? f2tf32(v1) : __float_as_uint(v1);
                }
            }
#pragma unroll
            for (int nt = 0; nt < 8; nt++)
#pragma unroll
                for (int mt = 0; mt < MT; mt++)
                    mma_tf32(acc[mt][nt][0], acc[mt][nt][1], acc[mt][nt][2], acc[mt][nt][3],
                             af[mt][0], af[mt][1], af[mt][2], af[mt][3],
                             bf[nt][0], bf[nt][1]);
        }
        __syncthreads();
    }

    // ---- epilogue ----
    float* Cp = C + coff;
    const float* Rp = resid ? (resid + coff) : (const float*)0;
    bool atom = (flags & 8) != 0;
    bool addb = (flags & 1) && (!atom || kspl == 0);
#pragma unroll
    for (int mt = 0; mt < MT; mt++) {
#pragma unroll
        for (int half = 0; half < 2; half++) {
            int rr = m0 + wm + mt * 16 + gr + half * 8;
#pragma unroll
            for (int nt = 0; nt < 8; nt++) {
                int cc = n0 + wn0 + nt * 8 + 2 * gc;
                float v0 = acc[mt][nt][half * 2 + 0];
                float v1 = acc[mt][nt][half * 2 + 1];
                size_t o = (size_t)rr * ldc + cc;
                if (flags & 32) {
                    if (cc < 512) { v0 += bias[cc]; v1 += bias[cc + 1]; }
                } else if (addb) { v0 += bias[cc]; v1 += bias[cc + 1]; }
                if (atom) {
                    atomicAdd(Cp + o, v0);
                    atomicAdd(Cp + o + 1, v1);
                } else {
                    if (flags & 2) { v0 += Rp[o]; v1 += Rp[o + 1]; }
                    if (flags & 4) {
                        v0 = 0.5f * v0 * (1.0f + erff(v0 * 0.70710678118654752f));
                        v1 = 0.5f * v1 * (1.0f + erff(v1 * 0.70710678118654752f));
                    }
                    if (flags & 16) { v0 = roundtf(v0); v1 = roundtf(v1); }
                    float2 w = { v0, v1 };
                    *(float2*)(Cp + o) = w;
                }
            }
        }
    }
}

// smem byte sizes per (NT, BT)
#define SMEM_128_0 ((2 * 128 * 36 + 2 * 128 * 36) * 4)
#define SMEM_128_1 ((2 * 128 * 36 + 2 * 32 * 136) * 4)
#define SMEM_64_1  ((2 * 128 * 36 + 2 * 32 * 72) * 4)

// ---------------------------------------------------------------------------
// In-place tf32 rounding pass (for atomic-built tensors): n multiple of 4096
// ---------------------------------------------------------------------------
__global__ void round_tf32_kernel(float* p, int n4) {
    int i = blockIdx.x * blockDim.x + threadIdx.x;
    if (i >= n4) return;
    float4 v = ((float4*)p)[i];
    v.x = roundtf(v.x); v.y = roundtf(v.y); v.z = roundtf(v.z); v.w = roundtf(v.w);
    ((float4*)p)[i] = v;
}

// ---------------------------------------------------------------------------
// LayerNorm: one block (256 threads) per row of D_=512; output tf32-rounded
// ---------------------------------------------------------------------------
__global__ void ln_kernel(const float* __restrict__ x,
                          const float* __restrict__ g,
                          const float* __restrict__ b,
                          float* __restrict__ out) {
    int row = blockIdx.x;
    int t = threadIdx.x;
    const float* xr = x + (size_t)row * D_;
    __shared__ float red[256];

    float v0 = xr[t];
    float v1 = xr[t + 256];
    red[t] = v0 + v1;
    __syncthreads();
    for (int o = 128; o > 0; o >>= 1) { if (t < o) red[t] += red[t + o]; __syncthreads(); }
    float mean = red[0] * (1.0f / D_);
    __syncthreads();

    float d0 = v0 - mean, d1 = v1 - mean;
    red[t] = d0 * d0 + d1 * d1;
    __syncthreads();
    for (int o = 128; o > 0; o >>= 1) { if (t < o) red[t] += red[t + o]; __syncthreads(); }
    float inv = rsqrtf(red[0] * (1.0f / D_) + 1e-5f);

    out[(size_t)row * D_ + t]       = roundtf(d0 * inv * g[t]       + b[t]);
    out[(size_t)row * D_ + t + 256] = roundtf(d1 * inv * g[t + 256] + b[t + 256]);
}

// ---------------------------------------------------------------------------
// Fused rel_shift gather + softmax over heads; vectorized 4 j per thread.
//   j <= i   : S[i, N-1-i+j];  j == i+1 : 0;  j > i+1 : S[i+1, j-i-2]
// ---------------------------------------------------------------------------
__global__ void softmax_shift_kernel(const float* __restrict__ AC,
                                     const float* __restrict__ S,
                                     float* __restrict__ attn) {
    int t = blockIdx.x * blockDim.x + threadIdx.x;
    if (t >= B_ * N_ * N_ / 4) return;
    int j = (t & (N_ / 4 - 1)) * 4;
    int i = (t >> 8) & (N_ - 1);
    int b = t >> 18;

    float vals[H_][4];
    float mx0 = -1e30f, mx1 = -1e30f, mx2 = -1e30f, mx3 = -1e30f;
#pragma unroll
    for (int h = 0; h < H_; h++) {
        size_t base = (size_t)(b * H_ + h) * N_;
        float4 ac = *(const float4*)&AC[(base + i) * N_ + j];
        float sv[4];
#pragma unroll
        for (int e = 0; e < 4; e++) {
            int jj = j + e;
            if (jj <= i)          sv[e] = __ldg(&S[(base + i) * N_ + (N_ - 1 - i + jj)]);
            else if (jj == i + 1) sv[e] = 0.f;
            else                  sv[e] = __ldg(&S[(base + i + 1) * N_ + (jj - i - 2)]);
        }
        vals[h][0] = (ac.x + sv[0] * (1.0f / 3.0f)) * SCALE_;
        vals[h][1] = (ac.y + sv[1] * (1.0f / 3.0f)) * SCALE_;
        vals[h][2] = (ac.z + sv[2] * (1.0f / 3.0f)) * SCALE_;
        vals[h][3] = (ac.w + sv[3] * (1.0f / 3.0f)) * SCALE_;
        mx0 = fmaxf(mx0, vals[h][0]); mx1 = fmaxf(mx1, vals[h][1]);
        mx2 = fmaxf(mx2, vals[h][2]); mx3 = fmaxf(mx3, vals[h][3]);
    }
    float s0 = 0.f, s1 = 0.f, s2 = 0.f, s3 = 0.f;
#pragma unroll
    for (int h = 0; h < H_; h++) {
        vals[h][0] = __expf(vals[h][0] - mx0); s0 += vals[h][0];
        vals[h][1] = __expf(vals[h][1] - mx1); s1 += vals[h][1];
        vals[h][2] = __expf(vals[h][2] - mx2); s2 += vals[h][2];
        vals[h][3] = __expf(vals[h][3] - mx3); s3 += vals[h][3];
    }
    s0 = 1.0f / s0; s1 = 1.0f / s1; s2 = 1.0f / s2; s3 = 1.0f / s3;
#pragma unroll
    for (int h = 0; h < H_; h++) {
        float4 w = { vals[h][0] * s0, vals[h][1] * s1, vals[h][2] * s2, vals[h][3] * s3 };
        *(float4*)&attn[((size_t)(b * H_ + h) * N_ + i) * N_ + j] = w;
    }
}

// ---------------------------------------------------------------------------
// Host-side orchestration
// ---------------------------------------------------------------------------
extern "C" void kernel_launch(void* const* d_in, const int* in_sizes, int n_in,
                              void* d_out, int out_size) {
    (void)in_sizes; (void)n_in; (void)out_size;
    const float* x       = (const float*)d_in[0];
    const float* r_t     = (const float*)d_in[1];
    const float* r_c     = (const float*)d_in[2];
    const float* r_p     = (const float*)d_in[3];
    const float* bias_pf = (const float*)d_in[4];
    const float* ln1_g   = (const float*)d_in[5];
    const float* ln1_b   = (const float*)d_in[6];
    const float* w_qkv   = (const float*)d_in[7];
    const float* w_out   = (const float*)d_in[8];
    const float* b_out   = (const float*)d_in[9];
    const float* w_kt    = (const float*)d_in[10];
    const float* w_kc    = (const float*)d_in[11];
    const float* w_kp    = (const float*)d_in[12];
    const float* ln2_g   = (const float*)d_in[13];
    const float* ln2_b   = (const float*)d_in[14];
    const float* w_ff1   = (const float*)d_in[15];
    const float* b_ff1   = (const float*)d_in[16];
    const float* w_ff2   = (const float*)d_in[17];
    const float* b_ff2   = (const float*)d_in[18];

    float* out      = (float*)d_out;
    float* attn_out = out + (size_t)BN_TOK * D_;

    float *xbuf, *xn, *qkv, *wsum, *AC, *S, *obh, *h1;
    cudaGetSymbolAddress((void**)&xbuf, g_xbuf);
    cudaGetSymbolAddress((void**)&xn,   g_xn);
    cudaGetSymbolAddress((void**)&qkv,  g_qkv);
    cudaGetSymbolAddress((void**)&wsum, g_wsum);
    cudaGetSymbolAddress((void**)&AC,   g_AC);
    cudaGetSymbolAddress((void**)&S,    g_S);
    cudaGetSymbolAddress((void**)&obh,  g_obh);
    cudaGetSymbolAddress((void**)&h1,   g_h1);

    static int smem_set = 0;
    if (!smem_set) {
        cudaFuncSetAttribute(mma_gemm<128,1,0,1>, cudaFuncAttributeMaxDynamicSharedMemorySize, SMEM_128_1);
        cudaFuncSetAttribute(mma_gemm<128,1,1,1>, cudaFuncAttributeMaxDynamicSharedMemorySize, SMEM_128_1);
        cudaFuncSetAttribute(mma_gemm<128,0,0,0>, cudaFuncAttributeMaxDynamicSharedMemorySize, SMEM_128_0);
        cudaFuncSetAttribute(mma_gemm<64,1,1,0>,  cudaFuncAttributeMaxDynamicSharedMemorySize, SMEM_64_1);
        smem_set = 1;
    }

    cudaMemcpyAsync(xbuf, x, sizeof(float) * BN_TOK * D_, cudaMemcpyDeviceToDevice);

    const long long NN = (long long)N_ * N_;
    const long long QKVB = (long long)N_ * 3 * HD_;

    for (int l = 0; l < DEPTH_; l++) {
        // ln1 -> xn (tf32-rounded)
        ln_kernel<<<BN_TOK, 256>>>(xbuf, ln1_g + l * D_, ln1_b + l * D_, xn);

        // qkv = xn @ w_qkv[l]; epilogue folds bias_pf into q cols and rounds all
        mma_gemm<128,1,0,1><<<dim3(12, 16, 1), 256, SMEM_128_1>>>(
            xn, 0, 0, w_qkv + (size_t)l * D_ * 3 * HD_, 0, 0,
            1, D_, D_, 3 * HD_, 1, 0, 0, 0, 0,
            qkv, 3 * HD_, 0, 0, bias_pf, 0, 32 | 16);

        // wsum = r_t@w_kt + r_c@w_kc + r_p@w_kp  (split-K x4, atomics), then round
        cudaMemsetAsync(wsum, 0, sizeof(float) * BN_TOK * HD_);
        mma_gemm<128,1,1,1><<<dim3(16, 16, 1), 256, SMEM_128_1>>>(
            r_t, r_c, r_p,
            w_kt + (size_t)l * D_ * HD_, w_kc + (size_t)l * D_ * HD_, w_kp + (size_t)l * D_ * HD_,
            3, D_, D_, HD_, 4, 0, 0, 0, 0,
            wsum, HD_, 0, 0, 0, 0, 8);
        round_tf32_kernel<<<BN_TOK * HD_ / 4 / 256, 256>>>(wsum, BN_TOK * HD_ / 4);

        // AC[b,h] = q' @ k^T  (operands pre-rounded: no cvt, ldmatrix)
        mma_gemm<128,0,0,0><<<dim3(8, 8, 16), 256, SMEM_128_0>>>(
            qkv, 0, 0, qkv + HD_, 0, 0,
            1, DH_, 3 * HD_, 3 * HD_, 1,
            QKVB, 64, QKVB, 64,
            AC, N_, 8 * NN, NN, 0, 0, 0);

        // S[b,h] = q' @ wsum^T
        mma_gemm<128,0,0,0><<<dim3(8, 8, 16), 256, SMEM_128_0>>>(
            qkv, 0, 0, wsum, 0, 0,
            1, DH_, 3 * HD_, HD_, 1,
            QKVB, 64, (long long)N_ * HD_, 64,
            S, N_, 8 * NN, NN, 0, 0, 0);

        // rel_shift + softmax over heads -> attn (output layout b,h,q,k)
        softmax_shift_kernel<<<B_ * N_ * N_ / 4 / 256, 256>>>(AC, S, attn_out);

        // obh = attn @ v  (split-K x4, atomics; v pre-rounded, attn cvt'd)
        cudaMemsetAsync(obh, 0, sizeof(float) * BN_TOK * HD_);
        mma_gemm<64,1,1,0><<<dim3(4, 8, 16), 256, SMEM_64_1>>>(
            attn_out, 0, 0, qkv + 2 * HD_, 0, 0,
            1, N_, N_, 3 * HD_, 4,
            8 * NN, NN, QKVB, 64,
            obh, HD_, (long long)N_ * HD_, 64, 0, 0, 8);
        round_tf32_kernel<<<BN_TOK * HD_ / 4 / 256, 256>>>(obh, BN_TOK * HD_ / 4);

        // x += obh @ w_out + b_out  (split-K x4, atomic into xbuf holding x)
        mma_gemm<128,1,0,1><<<dim3(16, 16, 1), 256, SMEM_128_1>>>(
            obh, 0, 0, w_out + (size_t)l * HD_ * D_, 0, 0,
            1, HD_, HD_, D_, 4, 0, 0, 0, 0,
            xbuf, D_, 0, 0, b_out + l * D_, 0, 9);

        // ln2 -> xn (rounded)
        ln_kernel<<<BN_TOK, 256>>>(xbuf, ln2_g + l * D_, ln2_b + l * D_, xn);

        // h1 = gelu(xn @ w_ff1 + b_ff1), rounded
        mma_gemm<128,1,0,1><<<dim3(16, 16, 1), 256, SMEM_128_1>>>(
            xn, 0, 0, w_ff1 + (size_t)l * D_ * FF_, 0, 0,
            1, D_, D_, FF_, 1, 0, 0, 0, 0,
            h1, FF_, 0, 0, b_ff1 + l * FF_, 0, 1 | 4 | 16);

        // x += h1 @ w_ff2 + b_ff2  (split-K x4, atomic into xbuf)
        mma_gemm<128,1,0,1><<<dim3(16, 16, 1), 256, SMEM_128_1>>>(
            h1, 0, 0, w_ff2 + (size_t)l * FF_ * D_, 0, 0,
            1, FF_, FF_, D_, 4, 0, 0, 0, 0,
            xbuf, D_, 0, 0, b_ff2 + l * D_, 0, 9);
    }

    cudaMemcpyAsync(out, xbuf, sizeof(float) * BN_TOK * D_, cudaMemcpyDeviceToDevice);
}